// round 10
// baseline (speedup 1.0000x reference)
#include <cuda_runtime.h>
#include <cuda_bf16.h>
#include <math.h>
#include <stdint.h>

// Problem constants
#define B_  2
#define S_  2048
#define HID_ 4096
#define NH_ 32
#define NKV_ 8
#define HD_ 128
#define M_TOT (B_ * S_)          // 4096
#define K3_ (3 * HID_)           // 12288 (split-concat K)
#define NKVD (NKV_ * HD_)        // 1024
#define NQKV (HID_ + 2 * NKVD)   // 6144 fused QKV output cols

// fp32 scratch
__device__ float g_q[(size_t)M_TOT * NH_ * HD_];
__device__ float g_k[(size_t)M_TOT * NKVD];
__device__ float g_v[(size_t)M_TOT * NKVD];
__device__ float g_o[(size_t)M_TOT * NH_ * HD_];

// split-bf16 scratch for projections
__device__ __nv_bfloat16 g_A2 [(size_t)M_TOT * K3_];
__device__ __nv_bfloat16 g_W3 [(size_t)NQKV  * K3_];   // fused [Wq;Wk;Wv]
__device__ __nv_bfloat16 g_Wo2[(size_t)HID_  * K3_];
__device__ __nv_bfloat16 g_O2 [(size_t)M_TOT * K3_];

// split-bf16 scratch for flash attention
__device__ __nv_bfloat16 g_qh [(size_t)M_TOT * NH_  * HD_];
__device__ __nv_bfloat16 g_ql [(size_t)M_TOT * NH_  * HD_];
__device__ __nv_bfloat16 g_kh [(size_t)M_TOT * NKVD];
__device__ __nv_bfloat16 g_kl [(size_t)M_TOT * NKVD];
__device__ __nv_bfloat16 g_vth[(size_t)M_TOT * NKVD];   // [b][kvh][d][s]
__device__ __nv_bfloat16 g_vtl[(size_t)M_TOT * NKVD];

// ---------------------------------------------------------------------------
struct alignas(8) BF4 { __nv_bfloat16 v[4]; };

// split3: fp32 [rows][K] -> bf16 [(row_ofs+rows)][3K]; mode 0: [H|L|H], mode 1: [H|H|L]
__global__ void split3_kernel(const float* __restrict__ src,
                              __nv_bfloat16* __restrict__ dst,
                              int K, int total4, int mode, int row_ofs) {
    int i = blockIdx.x * blockDim.x + threadIdx.x;
    if (i >= total4) return;
    int e = i * 4;
    int m = e / K;
    int k = e % K;
    float4 x = *(const float4*)(src + (size_t)e);
    BF4 H, L;
    float xs[4] = {x.x, x.y, x.z, x.w};
#pragma unroll
    for (int j = 0; j < 4; j++) {
        __nv_bfloat16 h = __float2bfloat16_rn(xs[j]);
        H.v[j] = h;
        L.v[j] = __float2bfloat16_rn(xs[j] - __bfloat162float(h));
    }
    size_t base = (size_t)(m + row_ofs) * (3 * K);
    *(BF4*)(dst + base + k) = H;
    if (mode == 0) {
        *(BF4*)(dst + base + K + k)     = L;
        *(BF4*)(dst + base + 2 * K + k) = H;
    } else {
        *(BF4*)(dst + base + K + k)     = H;
        *(BF4*)(dst + base + 2 * K + k) = L;
    }
}

// split2: fp32 -> (hi, lo) bf16, same layout, scaled by mul
__global__ void split2_kernel(const float* __restrict__ src,
                              __nv_bfloat16* __restrict__ dh,
                              __nv_bfloat16* __restrict__ dl,
                              float mul, int total4) {
    int i = blockIdx.x * blockDim.x + threadIdx.x;
    if (i >= total4) return;
    float4 x = *(const float4*)(src + (size_t)i * 4);
    float xs[4] = {x.x * mul, x.y * mul, x.z * mul, x.w * mul};
    BF4 H, L;
#pragma unroll
    for (int j = 0; j < 4; j++) {
        __nv_bfloat16 h = __float2bfloat16_rn(xs[j]);
        H.v[j] = h;
        L.v[j] = __float2bfloat16_rn(xs[j] - __bfloat162float(h));
    }
    *(BF4*)(dh + (size_t)i * 4) = H;
    *(BF4*)(dl + (size_t)i * 4) = L;
}

// V transpose+split: g_v [b*S+s][kvh][d] -> [b][kvh][d][s] hi/lo
__global__ void vt_kernel(const float* __restrict__ v,
                          __nv_bfloat16* __restrict__ th,
                          __nv_bfloat16* __restrict__ tl) {
    int i = blockIdx.x * blockDim.x + threadIdx.x;
    int s    = i % S_;
    int rest = i / S_;
    int d4   = rest % (HD_ / 4);
    rest    /= (HD_ / 4);
    int kvh  = rest % NKV_;
    int b    = rest / NKV_;
    float4 x = *(const float4*)(v + ((size_t)(b * S_ + s) * NKV_ + kvh) * HD_ + d4 * 4);
    float xs[4] = {x.x, x.y, x.z, x.w};
#pragma unroll
    for (int j = 0; j < 4; j++) {
        size_t o = ((size_t)(b * NKV_ + kvh) * HD_ + d4 * 4 + j) * S_ + s;
        __nv_bfloat16 h = __float2bfloat16_rn(xs[j]);
        th[o] = h;
        tl[o] = __float2bfloat16_rn(xs[j] - __bfloat162float(h));
    }
}

// ---------------------------------------------------------------------------
// mma / ldmatrix helpers
// ---------------------------------------------------------------------------
__device__ __forceinline__ void ldsm4(uint32_t* r, uint32_t addr) {
    asm volatile("ldmatrix.sync.aligned.m8n8.x4.shared.b16 {%0,%1,%2,%3}, [%4];\n"
                 : "=r"(r[0]), "=r"(r[1]), "=r"(r[2]), "=r"(r[3]) : "r"(addr));
}
__device__ __forceinline__ void mma_bf16(float* c, const uint32_t* a,
                                         uint32_t b0, uint32_t b1) {
    asm volatile("mma.sync.aligned.m16n8k16.row.col.f32.bf16.bf16.f32 "
                 "{%0,%1,%2,%3}, {%4,%5,%6,%7}, {%8,%9}, {%0,%1,%2,%3};\n"
                 : "+f"(c[0]), "+f"(c[1]), "+f"(c[2]), "+f"(c[3])
                 : "r"(a[0]), "r"(a[1]), "r"(a[2]), "r"(a[3]), "r"(b0), "r"(b1));
}
__device__ __forceinline__ uint32_t cvt_bf16x2(float lo, float hi) {
    uint32_t r;
    asm("cvt.rn.bf16x2.f32 %0, %1, %2;" : "=r"(r) : "f"(hi), "f"(lo));
    return r;
}

// ---------------------------------------------------------------------------
// bf16 tensor-core GEMM (NT): 128x128x32 tile, 256 threads, warp tile 64x32,
// 3-stage cp.async. All frags for both k-halves loaded up-front per kt to
// break ldsm->mma RAW stalls; then 32 back-to-back mmas.
// ---------------------------------------------------------------------------
#define HG_BK 32
#define HG_LDS 40
#define HG_STAGE_ELEMS (128 * HG_LDS)
#define HG_STAGE_BYTES (HG_STAGE_ELEMS * 2)

__global__ __launch_bounds__(256, 2) void hgemm_nt(
    const __nv_bfloat16* __restrict__ A, const __nv_bfloat16* __restrict__ B,
    float* __restrict__ C0, float* __restrict__ C1, float* __restrict__ C2,
    int M, int K) {
    __shared__ __nv_bfloat16 As[3][HG_STAGE_ELEMS];
    __shared__ __nv_bfloat16 Bs[3][HG_STAGE_ELEMS];

    const int t    = threadIdx.x;
    const int lane = t & 31;
    const int w    = t >> 5;
    const int wm   = w >> 2;
    const int wn   = w & 3;

    const __nv_bfloat16* Ab = A + (size_t)blockIdx.y * 128 * K;
    const __nv_bfloat16* Bb = B + (size_t)blockIdx.x * 128 * K;

    const uint32_t as0 = (uint32_t)__cvta_generic_to_shared(&As[0][0]);
    const uint32_t bs0 = (uint32_t)__cvta_generic_to_shared(&Bs[0][0]);

    const int ldr = t >> 2;
    const int ldc = (t & 3) * 8;

    auto load_tile = [&](int kt, int st) {
#pragma unroll
        for (int it = 0; it < 2; it++) {
            int r = ldr + it * 64;
            const __nv_bfloat16* ga = Ab + (size_t)r * K + kt * HG_BK + ldc;
            uint32_t sa = as0 + st * HG_STAGE_BYTES + (r * HG_LDS + ldc) * 2;
            asm volatile("cp.async.cg.shared.global [%0], [%1], 16;\n" :: "r"(sa), "l"(ga));
            const __nv_bfloat16* gb = Bb + (size_t)r * K + kt * HG_BK + ldc;
            uint32_t sb = bs0 + st * HG_STAGE_BYTES + (r * HG_LDS + ldc) * 2;
            asm volatile("cp.async.cg.shared.global [%0], [%1], 16;\n" :: "r"(sb), "l"(gb));
        }
    };

    const int KT = K / HG_BK;
    load_tile(0, 0);
    asm volatile("cp.async.commit_group;\n");
    load_tile(1, 1);
    asm volatile("cp.async.commit_group;\n");

    float acc[4][4][4];
#pragma unroll
    for (int i = 0; i < 4; i++)
#pragma unroll
        for (int j = 0; j < 4; j++)
#pragma unroll
            for (int r = 0; r < 4; r++) acc[i][j][r] = 0.f;

    const int g  = lane >> 3;
    const int lr = lane & 7;
    const int a_row = ((g & 1) << 3) + lr;
    const int a_k   = (g >> 1) << 3;
    const int b_row = ((g >> 1) << 3) + lr;
    const int b_k   = (g & 1) << 3;

    for (int kt = 0; kt < KT; kt++) {
        asm volatile("cp.async.wait_group 1;\n");
        __syncthreads();

        const int st = kt % 3;
        const uint32_t asb = as0 + st * HG_STAGE_BYTES;
        const uint32_t bsb = bs0 + st * HG_STAGE_BYTES;

        // issue ALL fragment loads for both k-halves first (12 ldsm.x4)
        uint32_t af[2][4][4];
        uint32_t bf_[2][4][2];
#pragma unroll
        for (int ks = 0; ks < 2; ks++) {
#pragma unroll
            for (int mf = 0; mf < 4; mf++) {
                int row = wm * 64 + mf * 16 + a_row;
                ldsm4(af[ks][mf], asb + (row * HG_LDS + ks * 16 + a_k) * 2);
            }
#pragma unroll
            for (int np = 0; np < 2; np++) {
                int row = wn * 32 + np * 16 + b_row;
                uint32_t tmp[4];
                ldsm4(tmp, bsb + (row * HG_LDS + ks * 16 + b_k) * 2);
                bf_[ks][np*2][0] = tmp[0]; bf_[ks][np*2][1] = tmp[1];
                bf_[ks][np*2+1][0] = tmp[2]; bf_[ks][np*2+1][1] = tmp[3];
            }
        }

        // then issue the next global load (stage freed at kt-1)
        if (kt + 2 < KT) load_tile(kt + 2, (kt + 2) % 3);
        asm volatile("cp.async.commit_group;\n");

        // 32 back-to-back mmas
#pragma unroll
        for (int ks = 0; ks < 2; ks++)
#pragma unroll
            for (int mf = 0; mf < 4; mf++)
#pragma unroll
                for (int nf = 0; nf < 4; nf++)
                    mma_bf16(acc[mf][nf], af[ks][mf], bf_[ks][nf][0], bf_[ks][nf][1]);
    }

    // epilogue with QKV column routing (Q: 4096 cols, K: 1024, V: 1024)
    const int gc0 = blockIdx.x * 128;
    float* Cd; int cstride, cbase;
    if (gc0 < HID_)                { Cd = C0; cstride = NH_ * HD_; cbase = 0; }
    else if (gc0 < HID_ + NKVD)    { Cd = C1; cstride = NKVD;      cbase = HID_; }
    else                           { Cd = C2; cstride = NKVD;      cbase = HID_ + NKVD; }

#pragma unroll
    for (int mf = 0; mf < 4; mf++) {
        int row = blockIdx.y * 128 + wm * 64 + mf * 16 + (lane >> 2);
#pragma unroll
        for (int nf = 0; nf < 4; nf++) {
            int col = gc0 + wn * 32 + nf * 8 + (lane & 3) * 2 - cbase;
            float2 v0 = {acc[mf][nf][0], acc[mf][nf][1]};
            float2 v1 = {acc[mf][nf][2], acc[mf][nf][3]};
            *(float2*)&Cd[(size_t)row * cstride + col]       = v0;
            *(float2*)&Cd[(size_t)(row + 8) * cstride + col] = v1;
        }
    }
}

// ---------------------------------------------------------------------------
// RoPE in-place on q [M,NH,HD] and k [M,NKV,HD]
// ---------------------------------------------------------------------------
#define ROPE_TOTAL (B_ * S_ * (NH_ + NKV_) * 64)

__global__ void rope_kernel(float* __restrict__ q, float* __restrict__ k,
                            const int* __restrict__ pos_ids) {
    int idx = blockIdx.x * blockDim.x + threadIdx.x;
    if (idx >= ROPE_TOTAL) return;
    int d    = idx & 63;
    int rest = idx >> 6;
    int head = rest % (NH_ + NKV_);
    rest    /= (NH_ + NKV_);
    int s = rest % S_;
    int b = rest / S_;

    float inv = powf(10000.0f, -(float)d * (1.0f / 64.0f));
    float ang = (float)pos_ids[s] * inv;
    float c = cosf(ang), sn = sinf(ang);

    float* base = (head < NH_)
        ? q + ((size_t)(b * S_ + s) * NH_  + head) * HD_
        : k + ((size_t)(b * S_ + s) * NKV_ + (head - NH_)) * HD_;

    float x1 = base[d], x2 = base[d + 64];
    base[d]      = x1 * c - x2 * sn;
    base[d + 64] = x2 * c + x1 * sn;
}

// ---------------------------------------------------------------------------
// Tensor-core flash attention (verified R5). BQ=128, BK=64, HD=128, 256 thr.
// ---------------------------------------------------------------------------
#define FQ_LDS 136
#define FV_LDS 72
#define F_QH 0
#define F_QL 17408
#define F_STAGE0 34816
#define F_STAGE (8704 + 8704 + 9216 + 9216)
#define F_KH 0
#define F_KL 8704
#define F_VTH 17408
#define F_VTL 26624
#define FLASH_SMEM_ELEMS (F_STAGE0 + 2 * F_STAGE)
#define FLASH_SMEM_BYTES (FLASH_SMEM_ELEMS * 2)

__global__ __launch_bounds__(256, 1) void flash_tc(
    const __nv_bfloat16* __restrict__ qh, const __nv_bfloat16* __restrict__ ql,
    const __nv_bfloat16* __restrict__ kh, const __nv_bfloat16* __restrict__ kl,
    const __nv_bfloat16* __restrict__ vth, const __nv_bfloat16* __restrict__ vtl,
    float* __restrict__ o) {
    const int qt  = gridDim.x - 1 - blockIdx.x;
    const int h   = blockIdx.y;
    const int b   = blockIdx.z;
    const int kvh = h >> 2;

    extern __shared__ __nv_bfloat16 fsm[];
    const uint32_t sb = (uint32_t)__cvta_generic_to_shared(fsm);

    const int t    = threadIdx.x;
    const int lane = t & 31;
    const int w    = t >> 5;

    {
        int r = t >> 1;
        const __nv_bfloat16* gq = qh + ((size_t)(b * S_ + qt * 128 + r) * NH_ + h) * HD_;
        const __nv_bfloat16* gl = ql + ((size_t)(b * S_ + qt * 128 + r) * NH_ + h) * HD_;
#pragma unroll
        for (int j = 0; j < 8; j++) {
            int col = (t & 1) * 64 + j * 8;
            uint32_t sh = sb + (F_QH + r * FQ_LDS + col) * 2;
            uint32_t sl = sb + (F_QL + r * FQ_LDS + col) * 2;
            asm volatile("cp.async.cg.shared.global [%0], [%1], 16;\n" :: "r"(sh), "l"(gq + col));
            asm volatile("cp.async.cg.shared.global [%0], [%1], 16;\n" :: "r"(sl), "l"(gl + col));
        }
        asm volatile("cp.async.commit_group;\n");
    }

    auto load_kv = [&](int kt, int st) {
        uint32_t stb = sb + (F_STAGE0 + st * F_STAGE) * 2;
        {
            int r  = t >> 2;
            int cb = (t & 3) * 32;
            size_t go = ((size_t)(b * S_ + kt * 64 + r) * NKV_ + kvh) * HD_;
#pragma unroll
            for (int j = 0; j < 4; j++) {
                int col = cb + j * 8;
                asm volatile("cp.async.cg.shared.global [%0], [%1], 16;\n"
                             :: "r"(stb + (F_KH + r * FQ_LDS + col) * 2), "l"(kh + go + col));
                asm volatile("cp.async.cg.shared.global [%0], [%1], 16;\n"
                             :: "r"(stb + (F_KL + r * FQ_LDS + col) * 2), "l"(kl + go + col));
            }
        }
        {
            int rv = t >> 1;
            int cv = (t & 1) * 32;
            size_t go = ((size_t)(b * NKV_ + kvh) * HD_ + rv) * S_ + kt * 64;
#pragma unroll
            for (int j = 0; j < 4; j++) {
                int col = cv + j * 8;
                asm volatile("cp.async.cg.shared.global [%0], [%1], 16;\n"
                             :: "r"(stb + (F_VTH + rv * FV_LDS + col) * 2), "l"(vth + go + col));
                asm volatile("cp.async.cg.shared.global [%0], [%1], 16;\n"
                             :: "r"(stb + (F_VTL + rv * FV_LDS + col) * 2), "l"(vtl + go + col));
            }
        }
    };

    const int ktmax = 2 * qt + 1;
    load_kv(0, 0);
    asm volatile("cp.async.commit_group;\n");
    if (ktmax >= 1) load_kv(1, 1);
    asm volatile("cp.async.commit_group;\n");

    const int g  = lane >> 3;
    const int lr = lane & 7;
    const int a_row = ((g & 1) << 3) + lr;
    const int a_k   = (g >> 1) << 3;
    const int b_row = ((g >> 1) << 3) + lr;
    const int b_k   = (g & 1) << 3;

    float out[16][4];
#pragma unroll
    for (int i = 0; i < 16; i++)
#pragma unroll
        for (int j = 0; j < 4; j++) out[i][j] = 0.f;
    float m0 = -INFINITY, m1 = -INFINITY, l0 = 0.f, l1 = 0.f;

    const int qrow_base = qt * 128 + w * 16;

    for (int kt = 0; kt <= ktmax; kt++) {
        asm volatile("cp.async.wait_group 1;\n");
        __syncthreads();
        const int st = kt & 1;
        const uint32_t stb = sb + (F_STAGE0 + st * F_STAGE) * 2;

        if (kt * 64 <= qrow_base + 15) {
            float accs[8][4];
#pragma unroll
            for (int i = 0; i < 8; i++)
#pragma unroll
                for (int j = 0; j < 4; j++) accs[i][j] = 0.f;

#pragma unroll
            for (int kc = 0; kc < 8; kc++) {
                uint32_t aH[4], aL[4];
                ldsm4(aH, sb + (F_QH + (w * 16 + a_row) * FQ_LDS + kc * 16 + a_k) * 2);
                ldsm4(aL, sb + (F_QL + (w * 16 + a_row) * FQ_LDS + kc * 16 + a_k) * 2);
#pragma unroll
                for (int nf2 = 0; nf2 < 4; nf2++) {
                    uint32_t bh[4], bl[4];
                    ldsm4(bh, stb + (F_KH + (nf2 * 16 + b_row) * FQ_LDS + kc * 16 + b_k) * 2);
                    mma_bf16(accs[nf2 * 2],     aH, bh[0], bh[1]);
                    mma_bf16(accs[nf2 * 2 + 1], aH, bh[2], bh[3]);
                    mma_bf16(accs[nf2 * 2],     aL, bh[0], bh[1]);
                    mma_bf16(accs[nf2 * 2 + 1], aL, bh[2], bh[3]);
                    ldsm4(bl, stb + (F_KL + (nf2 * 16 + b_row) * FQ_LDS + kc * 16 + b_k) * 2);
                    mma_bf16(accs[nf2 * 2],     aH, bl[0], bl[1]);
                    mma_bf16(accs[nf2 * 2 + 1], aH, bl[2], bl[3]);
                }
            }

            if (kt * 64 + 63 > qrow_base) {
                int r0 = qrow_base + (lane >> 2);
#pragma unroll
                for (int nf = 0; nf < 8; nf++) {
#pragma unroll
                    for (int e = 0; e < 4; e++) {
                        int col = kt * 64 + nf * 8 + (lane & 3) * 2 + (e & 1);
                        int row = r0 + (e >> 1) * 8;
                        if (col > row) accs[nf][e] = -1.0e30f;
                    }
                }
            }

            float mx0 = -INFINITY, mx1 = -INFINITY;
#pragma unroll
            for (int nf = 0; nf < 8; nf++) {
                mx0 = fmaxf(mx0, fmaxf(accs[nf][0], accs[nf][1]));
                mx1 = fmaxf(mx1, fmaxf(accs[nf][2], accs[nf][3]));
            }
            mx0 = fmaxf(mx0, __shfl_xor_sync(0xffffffffu, mx0, 1));
            mx0 = fmaxf(mx0, __shfl_xor_sync(0xffffffffu, mx0, 2));
            mx1 = fmaxf(mx1, __shfl_xor_sync(0xffffffffu, mx1, 1));
            mx1 = fmaxf(mx1, __shfl_xor_sync(0xffffffffu, mx1, 2));
            float mn0 = fmaxf(m0, mx0), mn1 = fmaxf(m1, mx1);
            float c0 = exp2f(m0 - mn0), c1 = exp2f(m1 - mn1);
            m0 = mn0; m1 = mn1;

            float s0 = 0.f, s1 = 0.f;
#pragma unroll
            for (int nf = 0; nf < 8; nf++) {
                accs[nf][0] = exp2f(accs[nf][0] - mn0);
                accs[nf][1] = exp2f(accs[nf][1] - mn0);
                accs[nf][2] = exp2f(accs[nf][2] - mn1);
                accs[nf][3] = exp2f(accs[nf][3] - mn1);
                s0 += accs[nf][0] + accs[nf][1];
                s1 += accs[nf][2] + accs[nf][3];
            }
            s0 += __shfl_xor_sync(0xffffffffu, s0, 1);
            s0 += __shfl_xor_sync(0xffffffffu, s0, 2);
            s1 += __shfl_xor_sync(0xffffffffu, s1, 1);
            s1 += __shfl_xor_sync(0xffffffffu, s1, 2);
            l0 = l0 * c0 + s0;
            l1 = l1 * c1 + s1;

            uint32_t pH[4][4], pL[4][4];
#pragma unroll
            for (int kc2 = 0; kc2 < 4; kc2++) {
#pragma unroll
                for (int q4 = 0; q4 < 4; q4++) {
                    int nf = kc2 * 2 + (q4 >> 1);
                    int e0 = (q4 & 1) * 2;
                    float p0 = accs[nf][e0], p1 = accs[nf][e0 + 1];
                    uint32_t hh = cvt_bf16x2(p0, p1);
                    __nv_bfloat162 h2 = *reinterpret_cast<__nv_bfloat162*>(&hh);
                    pH[kc2][q4] = hh;
                    pL[kc2][q4] = cvt_bf16x2(p0 - __bfloat162float(h2.x),
                                             p1 - __bfloat162float(h2.y));
                }
            }

#pragma unroll
            for (int i = 0; i < 16; i++) {
                out[i][0] *= c0; out[i][1] *= c0;
                out[i][2] *= c1; out[i][3] *= c1;
            }

#pragma unroll
            for (int kc2 = 0; kc2 < 4; kc2++) {
#pragma unroll
                for (int nd = 0; nd < 8; nd++) {
                    uint32_t bh[4], bl[4];
                    ldsm4(bh, stb + (F_VTH + (nd * 16 + b_row) * FV_LDS + kc2 * 16 + b_k) * 2);
                    mma_bf16(out[nd * 2],     pH[kc2], bh[0], bh[1]);
                    mma_bf16(out[nd * 2 + 1], pH[kc2], bh[2], bh[3]);
                    mma_bf16(out[nd * 2],     pL[kc2], bh[0], bh[1]);
                    mma_bf16(out[nd * 2 + 1], pL[kc2], bh[2], bh[3]);
                    ldsm4(bl, stb + (F_VTL + (nd * 16 + b_row) * FV_LDS + kc2 * 16 + b_k) * 2);
                    mma_bf16(out[nd * 2],     pH[kc2], bl[0], bl[1]);
                    mma_bf16(out[nd * 2 + 1], pH[kc2], bl[2], bl[3]);
                }
            }
        }

        __syncthreads();
        if (kt + 2 <= ktmax) load_kv(kt + 2, st);
        asm volatile("cp.async.commit_group;\n");
    }

    float inv0 = 1.0f / l0, inv1 = 1.0f / l1;
    int r0 = qt * 128 + w * 16 + (lane >> 2);
#pragma unroll
    for (int nfd = 0; nfd < 16; nfd++) {
        int col = nfd * 8 + (lane & 3) * 2;
        float2 v0 = {out[nfd][0] * inv0, out[nfd][1] * inv0};
        float2 v1 = {out[nfd][2] * inv1, out[nfd][3] * inv1};
        *(float2*)&o[((size_t)(b * S_ + r0) * NH_ + h) * HD_ + col]       = v0;
        *(float2*)&o[((size_t)(b * S_ + r0 + 8) * NH_ + h) * HD_ + col]   = v1;
    }
}

// ---------------------------------------------------------------------------
// Launch
// ---------------------------------------------------------------------------
extern "C" void kernel_launch(void* const* d_in, const int* in_sizes, int n_in,
                              void* d_out, int out_size) {
    const float* hidden = (const float*)d_in[0];
    const int*   pos    = (const int*)  d_in[2];
    const float* wq     = (const float*)d_in[3];
    const float* wk     = (const float*)d_in[4];
    const float* wv     = (const float*)d_in[5];
    const float* wo     = (const float*)d_in[6];
    float* out = (float*)d_out;

    float *qb, *kb, *vb, *ob;
    __nv_bfloat16 *a2, *w3, *wo2, *o2;
    __nv_bfloat16 *qhp, *qlp, *khp, *klp, *vthp, *vtlp;
    cudaGetSymbolAddress((void**)&qb, g_q);
    cudaGetSymbolAddress((void**)&kb, g_k);
    cudaGetSymbolAddress((void**)&vb, g_v);
    cudaGetSymbolAddress((void**)&ob, g_o);
    cudaGetSymbolAddress((void**)&a2, g_A2);
    cudaGetSymbolAddress((void**)&w3, g_W3);
    cudaGetSymbolAddress((void**)&wo2, g_Wo2);
    cudaGetSymbolAddress((void**)&o2, g_O2);
    cudaGetSymbolAddress((void**)&qhp, g_qh);
    cudaGetSymbolAddress((void**)&qlp, g_ql);
    cudaGetSymbolAddress((void**)&khp, g_kh);
    cudaGetSymbolAddress((void**)&klp, g_kl);
    cudaGetSymbolAddress((void**)&vthp, g_vth);
    cudaGetSymbolAddress((void**)&vtlp, g_vtl);

    const int big4   = (M_TOT * HID_) / 4;
    const int small4 = (NKVD * HID_) / 4;
    split3_kernel<<<(big4 + 255) / 256, 256>>>(hidden, a2, HID_, big4, 0, 0);
    split3_kernel<<<(big4 + 255) / 256, 256>>>(wq, w3, HID_, big4, 1, 0);
    split3_kernel<<<(small4 + 255) / 256, 256>>>(wk, w3, HID_, small4, 1, HID_);
    split3_kernel<<<(small4 + 255) / 256, 256>>>(wv, w3, HID_, small4, 1, HID_ + NKVD);
    split3_kernel<<<(big4 + 255) / 256, 256>>>(wo, wo2, HID_, big4, 1, 0);

    // fused QKV projection: N = 6144
    hgemm_nt<<<dim3(NQKV / 128, M_TOT / 128), 256>>>(a2, w3, qb, kb, vb, M_TOT, K3_);

    rope_kernel<<<(ROPE_TOTAL + 255) / 256, 256>>>(qb, kb, pos);

    const float QSC = 0.08838834764831845f * 1.4426950408889634f;
    const int q4 = (M_TOT * NH_ * HD_) / 4;
    const int k4 = (M_TOT * NKVD) / 4;
    split2_kernel<<<(q4 + 255) / 256, 256>>>(qb, qhp, qlp, QSC, q4);
    split2_kernel<<<(k4 + 255) / 256, 256>>>(kb, khp, klp, 1.0f, k4);
    vt_kernel<<<(B_ * NKV_ * (HD_ / 4) * S_ + 255) / 256, 256>>>(vb, vthp, vtlp);

    cudaFuncSetAttribute(flash_tc, cudaFuncAttributeMaxDynamicSharedMemorySize,
                         FLASH_SMEM_BYTES);
    flash_tc<<<dim3(S_ / 128, NH_, B_), 256, FLASH_SMEM_BYTES>>>(
        qhp, qlp, khp, klp, vthp, vtlp, ob);

    // output projection (all cols < 4096 -> routed to C0 = out)
    split3_kernel<<<(big4 + 255) / 256, 256>>>(ob, o2, HID_, big4, 0, 0);
    hgemm_nt<<<dim3(HID_ / 128, M_TOT / 128), 256>>>(o2, wo2, out, out, out, M_TOT, K3_);
}

// round 11
// speedup vs baseline: 1.3854x; 1.3854x over previous
#include <cuda_runtime.h>
#include <cuda_bf16.h>
#include <cuda_fp16.h>
#include <math.h>
#include <stdint.h>

// Problem constants
#define B_  2
#define S_  2048
#define HID_ 4096
#define NH_ 32
#define NKV_ 8
#define HD_ 128
#define M_TOT (B_ * S_)          // 4096
#define K2_ (2 * HID_)           // 8192 (fp16 2-term split-concat K)
#define NKVD (NKV_ * HD_)        // 1024
#define NQKV (HID_ + 2 * NKVD)   // 6144 fused QKV output cols

// fp32 scratch
__device__ float g_q[(size_t)M_TOT * NH_ * HD_];
__device__ float g_k[(size_t)M_TOT * NKVD];
__device__ float g_v[(size_t)M_TOT * NKVD];
__device__ float g_o[(size_t)M_TOT * NH_ * HD_];

// fp16 2-term scratch for projections
__device__ __half g_A2 [(size_t)M_TOT * K2_];   // activations [Ah|Al]
__device__ __half g_W3 [(size_t)NQKV  * K2_];   // fused weights [Bh|Bh]
__device__ __half g_Wo2[(size_t)HID_  * K2_];
__device__ __half g_O2 [(size_t)M_TOT * K2_];

// bf16 scratch for flash attention (3-term hi/lo, proven path)
__device__ __nv_bfloat16 g_qh [(size_t)M_TOT * NH_  * HD_];
__device__ __nv_bfloat16 g_ql [(size_t)M_TOT * NH_  * HD_];
__device__ __nv_bfloat16 g_kh [(size_t)M_TOT * NKVD];
__device__ __nv_bfloat16 g_kl [(size_t)M_TOT * NKVD];
__device__ __nv_bfloat16 g_vth[(size_t)M_TOT * NKVD];   // [b][kvh][d][s]
__device__ __nv_bfloat16 g_vtl[(size_t)M_TOT * NKVD];

// ---------------------------------------------------------------------------
struct alignas(8) HF4 { __half v[4]; };
struct alignas(8) BF4 { __nv_bfloat16 v[4]; };

// splitH: fp32 [rows][K] -> fp16 [(row_ofs+rows)][2K]
//   mode 0 (activation): [hi | lo]   mode 1 (weight): [hi | hi]
__global__ void splitH_kernel(const float* __restrict__ src,
                              __half* __restrict__ dst,
                              int K, int total4, int mode, int row_ofs) {
    int i = blockIdx.x * blockDim.x + threadIdx.x;
    if (i >= total4) return;
    int e = i * 4;
    int m = e / K;
    int k = e % K;
    float4 x = *(const float4*)(src + (size_t)e);
    HF4 H, L;
    float xs[4] = {x.x, x.y, x.z, x.w};
#pragma unroll
    for (int j = 0; j < 4; j++) {
        __half h = __float2half_rn(xs[j]);
        H.v[j] = h;
        L.v[j] = __float2half_rn(xs[j] - __half2float(h));
    }
    size_t base = (size_t)(m + row_ofs) * (2 * K);
    *(HF4*)(dst + base + k) = H;
    if (mode == 0) *(HF4*)(dst + base + K + k) = L;
    else           *(HF4*)(dst + base + K + k) = H;
}

// split2: fp32 -> (hi, lo) bf16, scaled by mul (flash preprocessing)
__global__ void split2_kernel(const float* __restrict__ src,
                              __nv_bfloat16* __restrict__ dh,
                              __nv_bfloat16* __restrict__ dl,
                              float mul, int total4) {
    int i = blockIdx.x * blockDim.x + threadIdx.x;
    if (i >= total4) return;
    float4 x = *(const float4*)(src + (size_t)i * 4);
    float xs[4] = {x.x * mul, x.y * mul, x.z * mul, x.w * mul};
    BF4 H, L;
#pragma unroll
    for (int j = 0; j < 4; j++) {
        __nv_bfloat16 h = __float2bfloat16_rn(xs[j]);
        H.v[j] = h;
        L.v[j] = __float2bfloat16_rn(xs[j] - __bfloat162float(h));
    }
    *(BF4*)(dh + (size_t)i * 4) = H;
    *(BF4*)(dl + (size_t)i * 4) = L;
}

// V transpose+split: g_v [b*S+s][kvh][d] -> [b][kvh][d][s] hi/lo
__global__ void vt_kernel(const float* __restrict__ v,
                          __nv_bfloat16* __restrict__ th,
                          __nv_bfloat16* __restrict__ tl) {
    int i = blockIdx.x * blockDim.x + threadIdx.x;
    int s    = i % S_;
    int rest = i / S_;
    int d4   = rest % (HD_ / 4);
    rest    /= (HD_ / 4);
    int kvh  = rest % NKV_;
    int b    = rest / NKV_;
    float4 x = *(const float4*)(v + ((size_t)(b * S_ + s) * NKV_ + kvh) * HD_ + d4 * 4);
    float xs[4] = {x.x, x.y, x.z, x.w};
#pragma unroll
    for (int j = 0; j < 4; j++) {
        size_t o = ((size_t)(b * NKV_ + kvh) * HD_ + d4 * 4 + j) * S_ + s;
        __nv_bfloat16 h = __float2bfloat16_rn(xs[j]);
        th[o] = h;
        tl[o] = __float2bfloat16_rn(xs[j] - __bfloat162float(h));
    }
}

// ---------------------------------------------------------------------------
// mma / ldmatrix helpers
// ---------------------------------------------------------------------------
__device__ __forceinline__ void ldsm4(uint32_t* r, uint32_t addr) {
    asm volatile("ldmatrix.sync.aligned.m8n8.x4.shared.b16 {%0,%1,%2,%3}, [%4];\n"
                 : "=r"(r[0]), "=r"(r[1]), "=r"(r[2]), "=r"(r[3]) : "r"(addr));
}
__device__ __forceinline__ void mma_bf16(float* c, const uint32_t* a,
                                         uint32_t b0, uint32_t b1) {
    asm volatile("mma.sync.aligned.m16n8k16.row.col.f32.bf16.bf16.f32 "
                 "{%0,%1,%2,%3}, {%4,%5,%6,%7}, {%8,%9}, {%0,%1,%2,%3};\n"
                 : "+f"(c[0]), "+f"(c[1]), "+f"(c[2]), "+f"(c[3])
                 : "r"(a[0]), "r"(a[1]), "r"(a[2]), "r"(a[3]), "r"(b0), "r"(b1));
}
__device__ __forceinline__ void mma_f16(float* c, const uint32_t* a,
                                        uint32_t b0, uint32_t b1) {
    asm volatile("mma.sync.aligned.m16n8k16.row.col.f32.f16.f16.f32 "
                 "{%0,%1,%2,%3}, {%4,%5,%6,%7}, {%8,%9}, {%0,%1,%2,%3};\n"
                 : "+f"(c[0]), "+f"(c[1]), "+f"(c[2]), "+f"(c[3])
                 : "r"(a[0]), "r"(a[1]), "r"(a[2]), "r"(a[3]), "r"(b0), "r"(b1));
}
__device__ __forceinline__ uint32_t cvt_bf16x2(float lo, float hi) {
    uint32_t r;
    asm("cvt.rn.bf16x2.f32 %0, %1, %2;" : "=r"(r) : "f"(hi), "f"(lo));
    return r;
}

// ---------------------------------------------------------------------------
// fp16 tensor-core GEMM (NT): 128x128x32 tile, 256 threads, warp tile 64x32,
// 3-stage cp.async (R9 inner loop). Epilogue routes 128-col tiles for QKV.
// ---------------------------------------------------------------------------
#define HG_BK 32
#define HG_LDS 40
#define HG_STAGE_ELEMS (128 * HG_LDS)
#define HG_STAGE_BYTES (HG_STAGE_ELEMS * 2)

__global__ __launch_bounds__(256, 2) void hgemm_nt(
    const __half* __restrict__ A, const __half* __restrict__ B,
    float* __restrict__ C0, float* __restrict__ C1, float* __restrict__ C2,
    int M, int K) {
    __shared__ __half As[3][HG_STAGE_ELEMS];
    __shared__ __half Bs[3][HG_STAGE_ELEMS];

    const int t    = threadIdx.x;
    const int lane = t & 31;
    const int w    = t >> 5;
    const int wm   = w >> 2;
    const int wn   = w & 3;

    const __half* Ab = A + (size_t)blockIdx.y * 128 * K;
    const __half* Bb = B + (size_t)blockIdx.x * 128 * K;

    const uint32_t as0 = (uint32_t)__cvta_generic_to_shared(&As[0][0]);
    const uint32_t bs0 = (uint32_t)__cvta_generic_to_shared(&Bs[0][0]);

    const int ldr = t >> 2;
    const int ldc = (t & 3) * 8;

    auto load_tile = [&](int kt, int st) {
#pragma unroll
        for (int it = 0; it < 2; it++) {
            int r = ldr + it * 64;
            const __half* ga = Ab + (size_t)r * K + kt * HG_BK + ldc;
            uint32_t sa = as0 + st * HG_STAGE_BYTES + (r * HG_LDS + ldc) * 2;
            asm volatile("cp.async.cg.shared.global [%0], [%1], 16;\n" :: "r"(sa), "l"(ga));
            const __half* gb = Bb + (size_t)r * K + kt * HG_BK + ldc;
            uint32_t sb = bs0 + st * HG_STAGE_BYTES + (r * HG_LDS + ldc) * 2;
            asm volatile("cp.async.cg.shared.global [%0], [%1], 16;\n" :: "r"(sb), "l"(gb));
        }
    };

    const int KT = K / HG_BK;
    load_tile(0, 0);
    asm volatile("cp.async.commit_group;\n");
    load_tile(1, 1);
    asm volatile("cp.async.commit_group;\n");

    float acc[4][4][4];
#pragma unroll
    for (int i = 0; i < 4; i++)
#pragma unroll
        for (int j = 0; j < 4; j++)
#pragma unroll
            for (int r = 0; r < 4; r++) acc[i][j][r] = 0.f;

    const int g  = lane >> 3;
    const int lr = lane & 7;
    const int a_row = ((g & 1) << 3) + lr;
    const int a_k   = (g >> 1) << 3;
    const int b_row = ((g >> 1) << 3) + lr;
    const int b_k   = (g & 1) << 3;

    for (int kt = 0; kt < KT; kt++) {
        asm volatile("cp.async.wait_group 1;\n");
        __syncthreads();
        if (kt + 2 < KT) load_tile(kt + 2, (kt + 2) % 3);
        asm volatile("cp.async.commit_group;\n");

        const int st = kt % 3;
        const uint32_t asb = as0 + st * HG_STAGE_BYTES;
        const uint32_t bsb = bs0 + st * HG_STAGE_BYTES;

#pragma unroll
        for (int ks = 0; ks < 2; ks++) {
            uint32_t af[4][4];
            uint32_t bf_[4][2];
#pragma unroll
            for (int mf = 0; mf < 4; mf++) {
                int row = wm * 64 + mf * 16 + a_row;
                ldsm4(af[mf], asb + (row * HG_LDS + ks * 16 + a_k) * 2);
            }
#pragma unroll
            for (int np = 0; np < 2; np++) {
                int row = wn * 32 + np * 16 + b_row;
                uint32_t tmp[4];
                ldsm4(tmp, bsb + (row * HG_LDS + ks * 16 + b_k) * 2);
                bf_[np*2][0] = tmp[0]; bf_[np*2][1] = tmp[1];
                bf_[np*2+1][0] = tmp[2]; bf_[np*2+1][1] = tmp[3];
            }
#pragma unroll
            for (int mf = 0; mf < 4; mf++)
#pragma unroll
                for (int nf = 0; nf < 4; nf++)
                    mma_f16(acc[mf][nf], af[mf], bf_[nf][0], bf_[nf][1]);
        }
    }

    // epilogue with QKV column routing (Q: 4096 cols, K: 1024, V: 1024)
    const int gc0 = blockIdx.x * 128;
    float* Cd; int cstride, cbase;
    if (gc0 < HID_)                { Cd = C0; cstride = NH_ * HD_; cbase = 0; }
    else if (gc0 < HID_ + NKVD)    { Cd = C1; cstride = NKVD;      cbase = HID_; }
    else                           { Cd = C2; cstride = NKVD;      cbase = HID_ + NKVD; }

#pragma unroll
    for (int mf = 0; mf < 4; mf++) {
        int row = blockIdx.y * 128 + wm * 64 + mf * 16 + (lane >> 2);
#pragma unroll
        for (int nf = 0; nf < 4; nf++) {
            int col = gc0 + wn * 32 + nf * 8 + (lane & 3) * 2 - cbase;
            float2 v0 = {acc[mf][nf][0], acc[mf][nf][1]};
            float2 v1 = {acc[mf][nf][2], acc[mf][nf][3]};
            *(float2*)&Cd[(size_t)row * cstride + col]       = v0;
            *(float2*)&Cd[(size_t)(row + 8) * cstride + col] = v1;
        }
    }
}

// ---------------------------------------------------------------------------
// RoPE in-place on q [M,NH,HD] and k [M,NKV,HD]
// ---------------------------------------------------------------------------
#define ROPE_TOTAL (B_ * S_ * (NH_ + NKV_) * 64)

__global__ void rope_kernel(float* __restrict__ q, float* __restrict__ k,
                            const int* __restrict__ pos_ids) {
    int idx = blockIdx.x * blockDim.x + threadIdx.x;
    if (idx >= ROPE_TOTAL) return;
    int d    = idx & 63;
    int rest = idx >> 6;
    int head = rest % (NH_ + NKV_);
    rest    /= (NH_ + NKV_);
    int s = rest % S_;
    int b = rest / S_;

    float inv = powf(10000.0f, -(float)d * (1.0f / 64.0f));
    float ang = (float)pos_ids[s] * inv;
    float c = cosf(ang), sn = sinf(ang);

    float* base = (head < NH_)
        ? q + ((size_t)(b * S_ + s) * NH_  + head) * HD_
        : k + ((size_t)(b * S_ + s) * NKV_ + (head - NH_)) * HD_;

    float x1 = base[d], x2 = base[d + 64];
    base[d]      = x1 * c - x2 * sn;
    base[d + 64] = x2 * c + x1 * sn;
}

// ---------------------------------------------------------------------------
// Tensor-core flash attention (verified R5). BQ=128, BK=64, HD=128, 256 thr.
// ---------------------------------------------------------------------------
#define FQ_LDS 136
#define FV_LDS 72
#define F_QH 0
#define F_QL 17408
#define F_STAGE0 34816
#define F_STAGE (8704 + 8704 + 9216 + 9216)
#define F_KH 0
#define F_KL 8704
#define F_VTH 17408
#define F_VTL 26624
#define FLASH_SMEM_ELEMS (F_STAGE0 + 2 * F_STAGE)
#define FLASH_SMEM_BYTES (FLASH_SMEM_ELEMS * 2)

__global__ __launch_bounds__(256, 1) void flash_tc(
    const __nv_bfloat16* __restrict__ qh, const __nv_bfloat16* __restrict__ ql,
    const __nv_bfloat16* __restrict__ kh, const __nv_bfloat16* __restrict__ kl,
    const __nv_bfloat16* __restrict__ vth, const __nv_bfloat16* __restrict__ vtl,
    float* __restrict__ o) {
    const int qt  = gridDim.x - 1 - blockIdx.x;
    const int h   = blockIdx.y;
    const int b   = blockIdx.z;
    const int kvh = h >> 2;

    extern __shared__ __nv_bfloat16 fsm[];
    const uint32_t sb = (uint32_t)__cvta_generic_to_shared(fsm);

    const int t    = threadIdx.x;
    const int lane = t & 31;
    const int w    = t >> 5;

    {
        int r = t >> 1;
        const __nv_bfloat16* gq = qh + ((size_t)(b * S_ + qt * 128 + r) * NH_ + h) * HD_;
        const __nv_bfloat16* gl = ql + ((size_t)(b * S_ + qt * 128 + r) * NH_ + h) * HD_;
#pragma unroll
        for (int j = 0; j < 8; j++) {
            int col = (t & 1) * 64 + j * 8;
            uint32_t sh = sb + (F_QH + r * FQ_LDS + col) * 2;
            uint32_t sl = sb + (F_QL + r * FQ_LDS + col) * 2;
            asm volatile("cp.async.cg.shared.global [%0], [%1], 16;\n" :: "r"(sh), "l"(gq + col));
            asm volatile("cp.async.cg.shared.global [%0], [%1], 16;\n" :: "r"(sl), "l"(gl + col));
        }
        asm volatile("cp.async.commit_group;\n");
    }

    auto load_kv = [&](int kt, int st) {
        uint32_t stb = sb + (F_STAGE0 + st * F_STAGE) * 2;
        {
            int r  = t >> 2;
            int cb = (t & 3) * 32;
            size_t go = ((size_t)(b * S_ + kt * 64 + r) * NKV_ + kvh) * HD_;
#pragma unroll
            for (int j = 0; j < 4; j++) {
                int col = cb + j * 8;
                asm volatile("cp.async.cg.shared.global [%0], [%1], 16;\n"
                             :: "r"(stb + (F_KH + r * FQ_LDS + col) * 2), "l"(kh + go + col));
                asm volatile("cp.async.cg.shared.global [%0], [%1], 16;\n"
                             :: "r"(stb + (F_KL + r * FQ_LDS + col) * 2), "l"(kl + go + col));
            }
        }
        {
            int rv = t >> 1;
            int cv = (t & 1) * 32;
            size_t go = ((size_t)(b * NKV_ + kvh) * HD_ + rv) * S_ + kt * 64;
#pragma unroll
            for (int j = 0; j < 4; j++) {
                int col = cv + j * 8;
                asm volatile("cp.async.cg.shared.global [%0], [%1], 16;\n"
                             :: "r"(stb + (F_VTH + rv * FV_LDS + col) * 2), "l"(vth + go + col));
                asm volatile("cp.async.cg.shared.global [%0], [%1], 16;\n"
                             :: "r"(stb + (F_VTL + rv * FV_LDS + col) * 2), "l"(vtl + go + col));
            }
        }
    };

    const int ktmax = 2 * qt + 1;
    load_kv(0, 0);
    asm volatile("cp.async.commit_group;\n");
    if (ktmax >= 1) load_kv(1, 1);
    asm volatile("cp.async.commit_group;\n");

    const int g  = lane >> 3;
    const int lr = lane & 7;
    const int a_row = ((g & 1) << 3) + lr;
    const int a_k   = (g >> 1) << 3;
    const int b_row = ((g >> 1) << 3) + lr;
    const int b_k   = (g & 1) << 3;

    float out[16][4];
#pragma unroll
    for (int i = 0; i < 16; i++)
#pragma unroll
        for (int j = 0; j < 4; j++) out[i][j] = 0.f;
    float m0 = -INFINITY, m1 = -INFINITY, l0 = 0.f, l1 = 0.f;

    const int qrow_base = qt * 128 + w * 16;

    for (int kt = 0; kt <= ktmax; kt++) {
        asm volatile("cp.async.wait_group 1;\n");
        __syncthreads();
        const int st = kt & 1;
        const uint32_t stb = sb + (F_STAGE0 + st * F_STAGE) * 2;

        if (kt * 64 <= qrow_base + 15) {
            float accs[8][4];
#pragma unroll
            for (int i = 0; i < 8; i++)
#pragma unroll
                for (int j = 0; j < 4; j++) accs[i][j] = 0.f;

#pragma unroll
            for (int kc = 0; kc < 8; kc++) {
                uint32_t aH[4], aL[4];
                ldsm4(aH, sb + (F_QH + (w * 16 + a_row) * FQ_LDS + kc * 16 + a_k) * 2);
                ldsm4(aL, sb + (F_QL + (w * 16 + a_row) * FQ_LDS + kc * 16 + a_k) * 2);
#pragma unroll
                for (int nf2 = 0; nf2 < 4; nf2++) {
                    uint32_t bh[4], bl[4];
                    ldsm4(bh, stb + (F_KH + (nf2 * 16 + b_row) * FQ_LDS + kc * 16 + b_k) * 2);
                    mma_bf16(accs[nf2 * 2],     aH, bh[0], bh[1]);
                    mma_bf16(accs[nf2 * 2 + 1], aH, bh[2], bh[3]);
                    mma_bf16(accs[nf2 * 2],     aL, bh[0], bh[1]);
                    mma_bf16(accs[nf2 * 2 + 1], aL, bh[2], bh[3]);
                    ldsm4(bl, stb + (F_KL + (nf2 * 16 + b_row) * FQ_LDS + kc * 16 + b_k) * 2);
                    mma_bf16(accs[nf2 * 2],     aH, bl[0], bl[1]);
                    mma_bf16(accs[nf2 * 2 + 1], aH, bl[2], bl[3]);
                }
            }

            if (kt * 64 + 63 > qrow_base) {
                int r0 = qrow_base + (lane >> 2);
#pragma unroll
                for (int nf = 0; nf < 8; nf++) {
#pragma unroll
                    for (int e = 0; e < 4; e++) {
                        int col = kt * 64 + nf * 8 + (lane & 3) * 2 + (e & 1);
                        int row = r0 + (e >> 1) * 8;
                        if (col > row) accs[nf][e] = -1.0e30f;
                    }
                }
            }

            float mx0 = -INFINITY, mx1 = -INFINITY;
#pragma unroll
            for (int nf = 0; nf < 8; nf++) {
                mx0 = fmaxf(mx0, fmaxf(accs[nf][0], accs[nf][1]));
                mx1 = fmaxf(mx1, fmaxf(accs[nf][2], accs[nf][3]));
            }
            mx0 = fmaxf(mx0, __shfl_xor_sync(0xffffffffu, mx0, 1));
            mx0 = fmaxf(mx0, __shfl_xor_sync(0xffffffffu, mx0, 2));
            mx1 = fmaxf(mx1, __shfl_xor_sync(0xffffffffu, mx1, 1));
            mx1 = fmaxf(mx1, __shfl_xor_sync(0xffffffffu, mx1, 2));
            float mn0 = fmaxf(m0, mx0), mn1 = fmaxf(m1, mx1);
            float c0 = exp2f(m0 - mn0), c1 = exp2f(m1 - mn1);
            m0 = mn0; m1 = mn1;

            float s0 = 0.f, s1 = 0.f;
#pragma unroll
            for (int nf = 0; nf < 8; nf++) {
                accs[nf][0] = exp2f(accs[nf][0] - mn0);
                accs[nf][1] = exp2f(accs[nf][1] - mn0);
                accs[nf][2] = exp2f(accs[nf][2] - mn1);
                accs[nf][3] = exp2f(accs[nf][3] - mn1);
                s0 += accs[nf][0] + accs[nf][1];
                s1 += accs[nf][2] + accs[nf][3];
            }
            s0 += __shfl_xor_sync(0xffffffffu, s0, 1);
            s0 += __shfl_xor_sync(0xffffffffu, s0, 2);
            s1 += __shfl_xor_sync(0xffffffffu, s1, 1);
            s1 += __shfl_xor_sync(0xffffffffu, s1, 2);
            l0 = l0 * c0 + s0;
            l1 = l1 * c1 + s1;

            uint32_t pH[4][4], pL[4][4];
#pragma unroll
            for (int kc2 = 0; kc2 < 4; kc2++) {
#pragma unroll
                for (int q4 = 0; q4 < 4; q4++) {
                    int nf = kc2 * 2 + (q4 >> 1);
                    int e0 = (q4 & 1) * 2;
                    float p0 = accs[nf][e0], p1 = accs[nf][e0 + 1];
                    uint32_t hh = cvt_bf16x2(p0, p1);
                    __nv_bfloat162 h2 = *reinterpret_cast<__nv_bfloat162*>(&hh);
                    pH[kc2][q4] = hh;
                    pL[kc2][q4] = cvt_bf16x2(p0 - __bfloat162float(h2.x),
                                             p1 - __bfloat162float(h2.y));
                }
            }

#pragma unroll
            for (int i = 0; i < 16; i++) {
                out[i][0] *= c0; out[i][1] *= c0;
                out[i][2] *= c1; out[i][3] *= c1;
            }

#pragma unroll
            for (int kc2 = 0; kc2 < 4; kc2++) {
#pragma unroll
                for (int nd = 0; nd < 8; nd++) {
                    uint32_t bh[4], bl[4];
                    ldsm4(bh, stb + (F_VTH + (nd * 16 + b_row) * FV_LDS + kc2 * 16 + b_k) * 2);
                    mma_bf16(out[nd * 2],     pH[kc2], bh[0], bh[1]);
                    mma_bf16(out[nd * 2 + 1], pH[kc2], bh[2], bh[3]);
                    mma_bf16(out[nd * 2],     pL[kc2], bh[0], bh[1]);
                    mma_bf16(out[nd * 2 + 1], pL[kc2], bh[2], bh[3]);
                    ldsm4(bl, stb + (F_VTL + (nd * 16 + b_row) * FV_LDS + kc2 * 16 + b_k) * 2);
                    mma_bf16(out[nd * 2],     pH[kc2], bl[0], bl[1]);
                    mma_bf16(out[nd * 2 + 1], pH[kc2], bl[2], bl[3]);
                }
            }
        }

        __syncthreads();
        if (kt + 2 <= ktmax) load_kv(kt + 2, st);
        asm volatile("cp.async.commit_group;\n");
    }

    float inv0 = 1.0f / l0, inv1 = 1.0f / l1;
    int r0 = qt * 128 + w * 16 + (lane >> 2);
#pragma unroll
    for (int nfd = 0; nfd < 16; nfd++) {
        int col = nfd * 8 + (lane & 3) * 2;
        float2 v0 = {out[nfd][0] * inv0, out[nfd][1] * inv0};
        float2 v1 = {out[nfd][2] * inv1, out[nfd][3] * inv1};
        *(float2*)&o[((size_t)(b * S_ + r0) * NH_ + h) * HD_ + col]       = v0;
        *(float2*)&o[((size_t)(b * S_ + r0 + 8) * NH_ + h) * HD_ + col]   = v1;
    }
}

// ---------------------------------------------------------------------------
// Launch
// ---------------------------------------------------------------------------
extern "C" void kernel_launch(void* const* d_in, const int* in_sizes, int n_in,
                              void* d_out, int out_size) {
    const float* hidden = (const float*)d_in[0];
    const int*   pos    = (const int*)  d_in[2];
    const float* wq     = (const float*)d_in[3];
    const float* wk     = (const float*)d_in[4];
    const float* wv     = (const float*)d_in[5];
    const float* wo     = (const float*)d_in[6];
    float* out = (float*)d_out;

    float *qb, *kb, *vb, *ob;
    __half *a2, *w3, *wo2, *o2;
    __nv_bfloat16 *qhp, *qlp, *khp, *klp, *vthp, *vtlp;
    cudaGetSymbolAddress((void**)&qb, g_q);
    cudaGetSymbolAddress((void**)&kb, g_k);
    cudaGetSymbolAddress((void**)&vb, g_v);
    cudaGetSymbolAddress((void**)&ob, g_o);
    cudaGetSymbolAddress((void**)&a2, g_A2);
    cudaGetSymbolAddress((void**)&w3, g_W3);
    cudaGetSymbolAddress((void**)&wo2, g_Wo2);
    cudaGetSymbolAddress((void**)&o2, g_O2);
    cudaGetSymbolAddress((void**)&qhp, g_qh);
    cudaGetSymbolAddress((void**)&qlp, g_ql);
    cudaGetSymbolAddress((void**)&khp, g_kh);
    cudaGetSymbolAddress((void**)&klp, g_kl);
    cudaGetSymbolAddress((void**)&vthp, g_vth);
    cudaGetSymbolAddress((void**)&vtlp, g_vtl);

    const int big4   = (M_TOT * HID_) / 4;
    const int small4 = (NKVD * HID_) / 4;
    splitH_kernel<<<(big4 + 255) / 256, 256>>>(hidden, a2, HID_, big4, 0, 0);
    splitH_kernel<<<(big4 + 255) / 256, 256>>>(wq, w3, HID_, big4, 1, 0);
    splitH_kernel<<<(small4 + 255) / 256, 256>>>(wk, w3, HID_, small4, 1, HID_);
    splitH_kernel<<<(small4 + 255) / 256, 256>>>(wv, w3, HID_, small4, 1, HID_ + NKVD);
    splitH_kernel<<<(big4 + 255) / 256, 256>>>(wo, wo2, HID_, big4, 1, 0);

    // fused QKV projection: N = 6144, K = 8192
    hgemm_nt<<<dim3(NQKV / 128, M_TOT / 128), 256>>>(a2, w3, qb, kb, vb, M_TOT, K2_);

    rope_kernel<<<(ROPE_TOTAL + 255) / 256, 256>>>(qb, kb, pos);

    const float QSC = 0.08838834764831845f * 1.4426950408889634f;
    const int q4 = (M_TOT * NH_ * HD_) / 4;
    const int k4 = (M_TOT * NKVD) / 4;
    split2_kernel<<<(q4 + 255) / 256, 256>>>(qb, qhp, qlp, QSC, q4);
    split2_kernel<<<(k4 + 255) / 256, 256>>>(kb, khp, klp, 1.0f, k4);
    vt_kernel<<<(B_ * NKV_ * (HD_ / 4) * S_ + 255) / 256, 256>>>(vb, vthp, vtlp);

    cudaFuncSetAttribute(flash_tc, cudaFuncAttributeMaxDynamicSharedMemorySize,
                         FLASH_SMEM_BYTES);
    flash_tc<<<dim3(S_ / 128, NH_, B_), 256, FLASH_SMEM_BYTES>>>(
        qhp, qlp, khp, klp, vthp, vtlp, ob);

    // output projection (all cols < 4096 -> routed to C0 = out)
    splitH_kernel<<<(big4 + 255) / 256, 256>>>(ob, o2, HID_, big4, 0, 0);
    hgemm_nt<<<dim3(HID_ / 128, M_TOT / 128), 256>>>(o2, wo2, out, out, out, M_TOT, K2_);
}

// round 12
// speedup vs baseline: 2.1284x; 1.5363x over previous
#include <cuda_runtime.h>
#include <cuda_bf16.h>
#include <cuda_fp16.h>
#include <math.h>
#include <stdint.h>

// Problem constants
#define B_  2
#define S_  2048
#define HID_ 4096
#define NH_ 32
#define NKV_ 8
#define HD_ 128
#define M_TOT (B_ * S_)          // 4096
#define NKVD (NKV_ * HD_)        // 1024
#define NQKV (HID_ + 2 * NKVD)   // 6144 fused QKV output cols

// fp32 scratch
__device__ float g_q[(size_t)M_TOT * NH_ * HD_];
__device__ float g_k[(size_t)M_TOT * NKVD];
__device__ float g_v[(size_t)M_TOT * NKVD];
__device__ float g_o[(size_t)M_TOT * NH_ * HD_];

// fp16 scratch for projections (single-term)
__device__ __half g_A2 [(size_t)M_TOT * HID_];
__device__ __half g_W3 [(size_t)NQKV  * HID_];   // fused [Wq;Wk;Wv]
__device__ __half g_Wo2[(size_t)HID_  * HID_];
__device__ __half g_O2 [(size_t)M_TOT * HID_];

// bf16 scratch for flash attention (3-term hi/lo, proven path)
__device__ __nv_bfloat16 g_qh [(size_t)M_TOT * NH_  * HD_];
__device__ __nv_bfloat16 g_ql [(size_t)M_TOT * NH_  * HD_];
__device__ __nv_bfloat16 g_kh [(size_t)M_TOT * NKVD];
__device__ __nv_bfloat16 g_kl [(size_t)M_TOT * NKVD];
__device__ __nv_bfloat16 g_vth[(size_t)M_TOT * NKVD];   // [b][kvh][d][s]
__device__ __nv_bfloat16 g_vtl[(size_t)M_TOT * NKVD];

// ---------------------------------------------------------------------------
struct alignas(8) HF4 { __half v[4]; };
struct alignas(8) BF4 { __nv_bfloat16 v[4]; };

// cvtH: fp32 -> fp16 flat
__global__ void cvtH_kernel(const float* __restrict__ src,
                            __half* __restrict__ dst, int total4) {
    int i = blockIdx.x * blockDim.x + threadIdx.x;
    if (i >= total4) return;
    float4 x = *(const float4*)(src + (size_t)i * 4);
    HF4 H;
    H.v[0] = __float2half_rn(x.x);
    H.v[1] = __float2half_rn(x.y);
    H.v[2] = __float2half_rn(x.z);
    H.v[3] = __float2half_rn(x.w);
    *(HF4*)(dst + (size_t)i * 4) = H;
}

// split2: fp32 -> (hi, lo) bf16, scaled by mul (flash preprocessing)
__global__ void split2_kernel(const float* __restrict__ src,
                              __nv_bfloat16* __restrict__ dh,
                              __nv_bfloat16* __restrict__ dl,
                              float mul, int total4) {
    int i = blockIdx.x * blockDim.x + threadIdx.x;
    if (i >= total4) return;
    float4 x = *(const float4*)(src + (size_t)i * 4);
    float xs[4] = {x.x * mul, x.y * mul, x.z * mul, x.w * mul};
    BF4 H, L;
#pragma unroll
    for (int j = 0; j < 4; j++) {
        __nv_bfloat16 h = __float2bfloat16_rn(xs[j]);
        H.v[j] = h;
        L.v[j] = __float2bfloat16_rn(xs[j] - __bfloat162float(h));
    }
    *(BF4*)(dh + (size_t)i * 4) = H;
    *(BF4*)(dl + (size_t)i * 4) = L;
}

// V transpose+split: g_v [b*S+s][kvh][d] -> [b][kvh][d][s] hi/lo
__global__ void vt_kernel(const float* __restrict__ v,
                          __nv_bfloat16* __restrict__ th,
                          __nv_bfloat16* __restrict__ tl) {
    int i = blockIdx.x * blockDim.x + threadIdx.x;
    int s    = i % S_;
    int rest = i / S_;
    int d4   = rest % (HD_ / 4);
    rest    /= (HD_ / 4);
    int kvh  = rest % NKV_;
    int b    = rest / NKV_;
    float4 x = *(const float4*)(v + ((size_t)(b * S_ + s) * NKV_ + kvh) * HD_ + d4 * 4);
    float xs[4] = {x.x, x.y, x.z, x.w};
#pragma unroll
    for (int j = 0; j < 4; j++) {
        size_t o = ((size_t)(b * NKV_ + kvh) * HD_ + d4 * 4 + j) * S_ + s;
        __nv_bfloat16 h = __float2bfloat16_rn(xs[j]);
        th[o] = h;
        tl[o] = __float2bfloat16_rn(xs[j] - __bfloat162float(h));
    }
}

// ---------------------------------------------------------------------------
// mma / ldmatrix helpers
// ---------------------------------------------------------------------------
__device__ __forceinline__ void ldsm4(uint32_t* r, uint32_t addr) {
    asm volatile("ldmatrix.sync.aligned.m8n8.x4.shared.b16 {%0,%1,%2,%3}, [%4];\n"
                 : "=r"(r[0]), "=r"(r[1]), "=r"(r[2]), "=r"(r[3]) : "r"(addr));
}
__device__ __forceinline__ void mma_bf16(float* c, const uint32_t* a,
                                         uint32_t b0, uint32_t b1) {
    asm volatile("mma.sync.aligned.m16n8k16.row.col.f32.bf16.bf16.f32 "
                 "{%0,%1,%2,%3}, {%4,%5,%6,%7}, {%8,%9}, {%0,%1,%2,%3};\n"
                 : "+f"(c[0]), "+f"(c[1]), "+f"(c[2]), "+f"(c[3])
                 : "r"(a[0]), "r"(a[1]), "r"(a[2]), "r"(a[3]), "r"(b0), "r"(b1));
}
__device__ __forceinline__ void mma_f16(float* c, const uint32_t* a,
                                        uint32_t b0, uint32_t b1) {
    asm volatile("mma.sync.aligned.m16n8k16.row.col.f32.f16.f16.f32 "
                 "{%0,%1,%2,%3}, {%4,%5,%6,%7}, {%8,%9}, {%0,%1,%2,%3};\n"
                 : "+f"(c[0]), "+f"(c[1]), "+f"(c[2]), "+f"(c[3])
                 : "r"(a[0]), "r"(a[1]), "r"(a[2]), "r"(a[3]), "r"(b0), "r"(b1));
}
__device__ __forceinline__ uint32_t cvt_bf16x2(float lo, float hi) {
    uint32_t r;
    asm("cvt.rn.bf16x2.f32 %0, %1, %2;" : "=r"(r) : "f"(hi), "f"(lo));
    return r;
}

// ---------------------------------------------------------------------------
// fp16 tensor-core GEMM (NT): 128x128x32 tile, 256 threads, warp tile 64x32,
// 3-stage cp.async. Epilogue routes 128-col tiles for QKV.
// ---------------------------------------------------------------------------
#define HG_BK 32
#define HG_LDS 40
#define HG_STAGE_ELEMS (128 * HG_LDS)
#define HG_STAGE_BYTES (HG_STAGE_ELEMS * 2)

__global__ __launch_bounds__(256, 2) void hgemm_nt(
    const __half* __restrict__ A, const __half* __restrict__ B,
    float* __restrict__ C0, float* __restrict__ C1, float* __restrict__ C2,
    int M, int K) {
    __shared__ __half As[3][HG_STAGE_ELEMS];
    __shared__ __half Bs[3][HG_STAGE_ELEMS];

    const int t    = threadIdx.x;
    const int lane = t & 31;
    const int w    = t >> 5;
    const int wm   = w >> 2;
    const int wn   = w & 3;

    const __half* Ab = A + (size_t)blockIdx.y * 128 * K;
    const __half* Bb = B + (size_t)blockIdx.x * 128 * K;

    const uint32_t as0 = (uint32_t)__cvta_generic_to_shared(&As[0][0]);
    const uint32_t bs0 = (uint32_t)__cvta_generic_to_shared(&Bs[0][0]);

    const int ldr = t >> 2;
    const int ldc = (t & 3) * 8;

    auto load_tile = [&](int kt, int st) {
#pragma unroll
        for (int it = 0; it < 2; it++) {
            int r = ldr + it * 64;
            const __half* ga = Ab + (size_t)r * K + kt * HG_BK + ldc;
            uint32_t sa = as0 + st * HG_STAGE_BYTES + (r * HG_LDS + ldc) * 2;
            asm volatile("cp.async.cg.shared.global [%0], [%1], 16;\n" :: "r"(sa), "l"(ga));
            const __half* gb = Bb + (size_t)r * K + kt * HG_BK + ldc;
            uint32_t sb = bs0 + st * HG_STAGE_BYTES + (r * HG_LDS + ldc) * 2;
            asm volatile("cp.async.cg.shared.global [%0], [%1], 16;\n" :: "r"(sb), "l"(gb));
        }
    };

    const int KT = K / HG_BK;
    load_tile(0, 0);
    asm volatile("cp.async.commit_group;\n");
    load_tile(1, 1);
    asm volatile("cp.async.commit_group;\n");

    float acc[4][4][4];
#pragma unroll
    for (int i = 0; i < 4; i++)
#pragma unroll
        for (int j = 0; j < 4; j++)
#pragma unroll
            for (int r = 0; r < 4; r++) acc[i][j][r] = 0.f;

    const int g  = lane >> 3;
    const int lr = lane & 7;
    const int a_row = ((g & 1) << 3) + lr;
    const int a_k   = (g >> 1) << 3;
    const int b_row = ((g >> 1) << 3) + lr;
    const int b_k   = (g & 1) << 3;

    for (int kt = 0; kt < KT; kt++) {
        asm volatile("cp.async.wait_group 1;\n");
        __syncthreads();
        if (kt + 2 < KT) load_tile(kt + 2, (kt + 2) % 3);
        asm volatile("cp.async.commit_group;\n");

        const int st = kt % 3;
        const uint32_t asb = as0 + st * HG_STAGE_BYTES;
        const uint32_t bsb = bs0 + st * HG_STAGE_BYTES;

#pragma unroll
        for (int ks = 0; ks < 2; ks++) {
            uint32_t af[4][4];
            uint32_t bf_[4][2];
#pragma unroll
            for (int mf = 0; mf < 4; mf++) {
                int row = wm * 64 + mf * 16 + a_row;
                ldsm4(af[mf], asb + (row * HG_LDS + ks * 16 + a_k) * 2);
            }
#pragma unroll
            for (int np = 0; np < 2; np++) {
                int row = wn * 32 + np * 16 + b_row;
                uint32_t tmp[4];
                ldsm4(tmp, bsb + (row * HG_LDS + ks * 16 + b_k) * 2);
                bf_[np*2][0] = tmp[0]; bf_[np*2][1] = tmp[1];
                bf_[np*2+1][0] = tmp[2]; bf_[np*2+1][1] = tmp[3];
            }
#pragma unroll
            for (int mf = 0; mf < 4; mf++)
#pragma unroll
                for (int nf = 0; nf < 4; nf++)
                    mma_f16(acc[mf][nf], af[mf], bf_[nf][0], bf_[nf][1]);
        }
    }

    // epilogue with QKV column routing (Q: 4096 cols, K: 1024, V: 1024)
    const int gc0 = blockIdx.x * 128;
    float* Cd; int cstride, cbase;
    if (gc0 < HID_)                { Cd = C0; cstride = NH_ * HD_; cbase = 0; }
    else if (gc0 < HID_ + NKVD)    { Cd = C1; cstride = NKVD;      cbase = HID_; }
    else                           { Cd = C2; cstride = NKVD;      cbase = HID_ + NKVD; }

#pragma unroll
    for (int mf = 0; mf < 4; mf++) {
        int row = blockIdx.y * 128 + wm * 64 + mf * 16 + (lane >> 2);
#pragma unroll
        for (int nf = 0; nf < 4; nf++) {
            int col = gc0 + wn * 32 + nf * 8 + (lane & 3) * 2 - cbase;
            float2 v0 = {acc[mf][nf][0], acc[mf][nf][1]};
            float2 v1 = {acc[mf][nf][2], acc[mf][nf][3]};
            *(float2*)&Cd[(size_t)row * cstride + col]       = v0;
            *(float2*)&Cd[(size_t)(row + 8) * cstride + col] = v1;
        }
    }
}

// ---------------------------------------------------------------------------
// RoPE in-place on q [M,NH,HD] and k [M,NKV,HD]
// ---------------------------------------------------------------------------
#define ROPE_TOTAL (B_ * S_ * (NH_ + NKV_) * 64)

__global__ void rope_kernel(float* __restrict__ q, float* __restrict__ k,
                            const int* __restrict__ pos_ids) {
    int idx = blockIdx.x * blockDim.x + threadIdx.x;
    if (idx >= ROPE_TOTAL) return;
    int d    = idx & 63;
    int rest = idx >> 6;
    int head = rest % (NH_ + NKV_);
    rest    /= (NH_ + NKV_);
    int s = rest % S_;
    int b = rest / S_;

    float inv = powf(10000.0f, -(float)d * (1.0f / 64.0f));
    float ang = (float)pos_ids[s] * inv;
    float c = cosf(ang), sn = sinf(ang);

    float* base = (head < NH_)
        ? q + ((size_t)(b * S_ + s) * NH_  + head) * HD_
        : k + ((size_t)(b * S_ + s) * NKV_ + (head - NH_)) * HD_;

    float x1 = base[d], x2 = base[d + 64];
    base[d]      = x1 * c - x2 * sn;
    base[d + 64] = x2 * c + x1 * sn;
}

// ---------------------------------------------------------------------------
// Tensor-core flash attention (verified R5). BQ=128, BK=64, HD=128, 256 thr.
// ---------------------------------------------------------------------------
#define FQ_LDS 136
#define FV_LDS 72
#define F_QH 0
#define F_QL 17408
#define F_STAGE0 34816
#define F_STAGE (8704 + 8704 + 9216 + 9216)
#define F_KH 0
#define F_KL 8704
#define F_VTH 17408
#define F_VTL 26624
#define FLASH_SMEM_ELEMS (F_STAGE0 + 2 * F_STAGE)
#define FLASH_SMEM_BYTES (FLASH_SMEM_ELEMS * 2)

__global__ __launch_bounds__(256, 1) void flash_tc(
    const __nv_bfloat16* __restrict__ qh, const __nv_bfloat16* __restrict__ ql,
    const __nv_bfloat16* __restrict__ kh, const __nv_bfloat16* __restrict__ kl,
    const __nv_bfloat16* __restrict__ vth, const __nv_bfloat16* __restrict__ vtl,
    float* __restrict__ o) {
    const int qt  = gridDim.x - 1 - blockIdx.x;
    const int h   = blockIdx.y;
    const int b   = blockIdx.z;
    const int kvh = h >> 2;

    extern __shared__ __nv_bfloat16 fsm[];
    const uint32_t sb = (uint32_t)__cvta_generic_to_shared(fsm);

    const int t    = threadIdx.x;
    const int lane = t & 31;
    const int w    = t >> 5;

    {
        int r = t >> 1;
        const __nv_bfloat16* gq = qh + ((size_t)(b * S_ + qt * 128 + r) * NH_ + h) * HD_;
        const __nv_bfloat16* gl = ql + ((size_t)(b * S_ + qt * 128 + r) * NH_ + h) * HD_;
#pragma unroll
        for (int j = 0; j < 8; j++) {
            int col = (t & 1) * 64 + j * 8;
            uint32_t sh = sb + (F_QH + r * FQ_LDS + col) * 2;
            uint32_t sl = sb + (F_QL + r * FQ_LDS + col) * 2;
            asm volatile("cp.async.cg.shared.global [%0], [%1], 16;\n" :: "r"(sh), "l"(gq + col));
            asm volatile("cp.async.cg.shared.global [%0], [%1], 16;\n" :: "r"(sl), "l"(gl + col));
        }
        asm volatile("cp.async.commit_group;\n");
    }

    auto load_kv = [&](int kt, int st) {
        uint32_t stb = sb + (F_STAGE0 + st * F_STAGE) * 2;
        {
            int r  = t >> 2;
            int cb = (t & 3) * 32;
            size_t go = ((size_t)(b * S_ + kt * 64 + r) * NKV_ + kvh) * HD_;
#pragma unroll
            for (int j = 0; j < 4; j++) {
                int col = cb + j * 8;
                asm volatile("cp.async.cg.shared.global [%0], [%1], 16;\n"
                             :: "r"(stb + (F_KH + r * FQ_LDS + col) * 2), "l"(kh + go + col));
                asm volatile("cp.async.cg.shared.global [%0], [%1], 16;\n"
                             :: "r"(stb + (F_KL + r * FQ_LDS + col) * 2), "l"(kl + go + col));
            }
        }
        {
            int rv = t >> 1;
            int cv = (t & 1) * 32;
            size_t go = ((size_t)(b * NKV_ + kvh) * HD_ + rv) * S_ + kt * 64;
#pragma unroll
            for (int j = 0; j < 4; j++) {
                int col = cv + j * 8;
                asm volatile("cp.async.cg.shared.global [%0], [%1], 16;\n"
                             :: "r"(stb + (F_VTH + rv * FV_LDS + col) * 2), "l"(vth + go + col));
                asm volatile("cp.async.cg.shared.global [%0], [%1], 16;\n"
                             :: "r"(stb + (F_VTL + rv * FV_LDS + col) * 2), "l"(vtl + go + col));
            }
        }
    };

    const int ktmax = 2 * qt + 1;
    load_kv(0, 0);
    asm volatile("cp.async.commit_group;\n");
    if (ktmax >= 1) load_kv(1, 1);
    asm volatile("cp.async.commit_group;\n");

    const int g  = lane >> 3;
    const int lr = lane & 7;
    const int a_row = ((g & 1) << 3) + lr;
    const int a_k   = (g >> 1) << 3;
    const int b_row = ((g >> 1) << 3) + lr;
    const int b_k   = (g & 1) << 3;

    float out[16][4];
#pragma unroll
    for (int i = 0; i < 16; i++)
#pragma unroll
        for (int j = 0; j < 4; j++) out[i][j] = 0.f;
    float m0 = -INFINITY, m1 = -INFINITY, l0 = 0.f, l1 = 0.f;

    const int qrow_base = qt * 128 + w * 16;

    for (int kt = 0; kt <= ktmax; kt++) {
        asm volatile("cp.async.wait_group 1;\n");
        __syncthreads();
        const int st = kt & 1;
        const uint32_t stb = sb + (F_STAGE0 + st * F_STAGE) * 2;

        if (kt * 64 <= qrow_base + 15) {
            float accs[8][4];
#pragma unroll
            for (int i = 0; i < 8; i++)
#pragma unroll
                for (int j = 0; j < 4; j++) accs[i][j] = 0.f;

#pragma unroll
            for (int kc = 0; kc < 8; kc++) {
                uint32_t aH[4], aL[4];
                ldsm4(aH, sb + (F_QH + (w * 16 + a_row) * FQ_LDS + kc * 16 + a_k) * 2);
                ldsm4(aL, sb + (F_QL + (w * 16 + a_row) * FQ_LDS + kc * 16 + a_k) * 2);
#pragma unroll
                for (int nf2 = 0; nf2 < 4; nf2++) {
                    uint32_t bh[4], bl[4];
                    ldsm4(bh, stb + (F_KH + (nf2 * 16 + b_row) * FQ_LDS + kc * 16 + b_k) * 2);
                    mma_bf16(accs[nf2 * 2],     aH, bh[0], bh[1]);
                    mma_bf16(accs[nf2 * 2 + 1], aH, bh[2], bh[3]);
                    mma_bf16(accs[nf2 * 2],     aL, bh[0], bh[1]);
                    mma_bf16(accs[nf2 * 2 + 1], aL, bh[2], bh[3]);
                    ldsm4(bl, stb + (F_KL + (nf2 * 16 + b_row) * FQ_LDS + kc * 16 + b_k) * 2);
                    mma_bf16(accs[nf2 * 2],     aH, bl[0], bl[1]);
                    mma_bf16(accs[nf2 * 2 + 1], aH, bl[2], bl[3]);
                }
            }

            if (kt * 64 + 63 > qrow_base) {
                int r0 = qrow_base + (lane >> 2);
#pragma unroll
                for (int nf = 0; nf < 8; nf++) {
#pragma unroll
                    for (int e = 0; e < 4; e++) {
                        int col = kt * 64 + nf * 8 + (lane & 3) * 2 + (e & 1);
                        int row = r0 + (e >> 1) * 8;
                        if (col > row) accs[nf][e] = -1.0e30f;
                    }
                }
            }

            float mx0 = -INFINITY, mx1 = -INFINITY;
#pragma unroll
            for (int nf = 0; nf < 8; nf++) {
                mx0 = fmaxf(mx0, fmaxf(accs[nf][0], accs[nf][1]));
                mx1 = fmaxf(mx1, fmaxf(accs[nf][2], accs[nf][3]));
            }
            mx0 = fmaxf(mx0, __shfl_xor_sync(0xffffffffu, mx0, 1));
            mx0 = fmaxf(mx0, __shfl_xor_sync(0xffffffffu, mx0, 2));
            mx1 = fmaxf(mx1, __shfl_xor_sync(0xffffffffu, mx1, 1));
            mx1 = fmaxf(mx1, __shfl_xor_sync(0xffffffffu, mx1, 2));
            float mn0 = fmaxf(m0, mx0), mn1 = fmaxf(m1, mx1);
            float c0 = exp2f(m0 - mn0), c1 = exp2f(m1 - mn1);
            m0 = mn0; m1 = mn1;

            float s0 = 0.f, s1 = 0.f;
#pragma unroll
            for (int nf = 0; nf < 8; nf++) {
                accs[nf][0] = exp2f(accs[nf][0] - mn0);
                accs[nf][1] = exp2f(accs[nf][1] - mn0);
                accs[nf][2] = exp2f(accs[nf][2] - mn1);
                accs[nf][3] = exp2f(accs[nf][3] - mn1);
                s0 += accs[nf][0] + accs[nf][1];
                s1 += accs[nf][2] + accs[nf][3];
            }
            s0 += __shfl_xor_sync(0xffffffffu, s0, 1);
            s0 += __shfl_xor_sync(0xffffffffu, s0, 2);
            s1 += __shfl_xor_sync(0xffffffffu, s1, 1);
            s1 += __shfl_xor_sync(0xffffffffu, s1, 2);
            l0 = l0 * c0 + s0;
            l1 = l1 * c1 + s1;

            uint32_t pH[4][4], pL[4][4];
#pragma unroll
            for (int kc2 = 0; kc2 < 4; kc2++) {
#pragma unroll
                for (int q4 = 0; q4 < 4; q4++) {
                    int nf = kc2 * 2 + (q4 >> 1);
                    int e0 = (q4 & 1) * 2;
                    float p0 = accs[nf][e0], p1 = accs[nf][e0 + 1];
                    uint32_t hh = cvt_bf16x2(p0, p1);
                    __nv_bfloat162 h2 = *reinterpret_cast<__nv_bfloat162*>(&hh);
                    pH[kc2][q4] = hh;
                    pL[kc2][q4] = cvt_bf16x2(p0 - __bfloat162float(h2.x),
                                             p1 - __bfloat162float(h2.y));
                }
            }

#pragma unroll
            for (int i = 0; i < 16; i++) {
                out[i][0] *= c0; out[i][1] *= c0;
                out[i][2] *= c1; out[i][3] *= c1;
            }

#pragma unroll
            for (int kc2 = 0; kc2 < 4; kc2++) {
#pragma unroll
                for (int nd = 0; nd < 8; nd++) {
                    uint32_t bh[4], bl[4];
                    ldsm4(bh, stb + (F_VTH + (nd * 16 + b_row) * FV_LDS + kc2 * 16 + b_k) * 2);
                    mma_bf16(out[nd * 2],     pH[kc2], bh[0], bh[1]);
                    mma_bf16(out[nd * 2 + 1], pH[kc2], bh[2], bh[3]);
                    mma_bf16(out[nd * 2],     pL[kc2], bh[0], bh[1]);
                    mma_bf16(out[nd * 2 + 1], pL[kc2], bh[2], bh[3]);
                    ldsm4(bl, stb + (F_VTL + (nd * 16 + b_row) * FV_LDS + kc2 * 16 + b_k) * 2);
                    mma_bf16(out[nd * 2],     pH[kc2], bl[0], bl[1]);
                    mma_bf16(out[nd * 2 + 1], pH[kc2], bl[2], bl[3]);
                }
            }
        }

        __syncthreads();
        if (kt + 2 <= ktmax) load_kv(kt + 2, st);
        asm volatile("cp.async.commit_group;\n");
    }

    float inv0 = 1.0f / l0, inv1 = 1.0f / l1;
    int r0 = qt * 128 + w * 16 + (lane >> 2);
#pragma unroll
    for (int nfd = 0; nfd < 16; nfd++) {
        int col = nfd * 8 + (lane & 3) * 2;
        float2 v0 = {out[nfd][0] * inv0, out[nfd][1] * inv0};
        float2 v1 = {out[nfd][2] * inv1, out[nfd][3] * inv1};
        *(float2*)&o[((size_t)(b * S_ + r0) * NH_ + h) * HD_ + col]       = v0;
        *(float2*)&o[((size_t)(b * S_ + r0 + 8) * NH_ + h) * HD_ + col]   = v1;
    }
}

// ---------------------------------------------------------------------------
// Launch
// ---------------------------------------------------------------------------
extern "C" void kernel_launch(void* const* d_in, const int* in_sizes, int n_in,
                              void* d_out, int out_size) {
    const float* hidden = (const float*)d_in[0];
    const int*   pos    = (const int*)  d_in[2];
    const float* wq     = (const float*)d_in[3];
    const float* wk     = (const float*)d_in[4];
    const float* wv     = (const float*)d_in[5];
    const float* wo     = (const float*)d_in[6];
    float* out = (float*)d_out;

    float *qb, *kb, *vb, *ob;
    __half *a2, *w3, *wo2, *o2;
    __nv_bfloat16 *qhp, *qlp, *khp, *klp, *vthp, *vtlp;
    cudaGetSymbolAddress((void**)&qb, g_q);
    cudaGetSymbolAddress((void**)&kb, g_k);
    cudaGetSymbolAddress((void**)&vb, g_v);
    cudaGetSymbolAddress((void**)&ob, g_o);
    cudaGetSymbolAddress((void**)&a2, g_A2);
    cudaGetSymbolAddress((void**)&w3, g_W3);
    cudaGetSymbolAddress((void**)&wo2, g_Wo2);
    cudaGetSymbolAddress((void**)&o2, g_O2);
    cudaGetSymbolAddress((void**)&qhp, g_qh);
    cudaGetSymbolAddress((void**)&qlp, g_ql);
    cudaGetSymbolAddress((void**)&khp, g_kh);
    cudaGetSymbolAddress((void**)&klp, g_kl);
    cudaGetSymbolAddress((void**)&vthp, g_vth);
    cudaGetSymbolAddress((void**)&vtlp, g_vtl);

    const int big4   = (M_TOT * HID_) / 4;
    const int small4 = (NKVD * HID_) / 4;
    cvtH_kernel<<<(big4 + 255) / 256, 256>>>(hidden, a2, big4);
    cvtH_kernel<<<(big4 + 255) / 256, 256>>>(wq, w3, big4);
    cvtH_kernel<<<(small4 + 255) / 256, 256>>>(wk, w3 + (size_t)HID_ * HID_, small4);
    cvtH_kernel<<<(small4 + 255) / 256, 256>>>(wv, w3 + (size_t)(HID_ + NKVD) * HID_, small4);
    cvtH_kernel<<<(big4 + 255) / 256, 256>>>(wo, wo2, big4);

    // fused QKV projection: N = 6144, K = 4096
    hgemm_nt<<<dim3(NQKV / 128, M_TOT / 128), 256>>>(a2, w3, qb, kb, vb, M_TOT, HID_);

    rope_kernel<<<(ROPE_TOTAL + 255) / 256, 256>>>(qb, kb, pos);

    const float QSC = 0.08838834764831845f * 1.4426950408889634f;
    const int q4 = (M_TOT * NH_ * HD_) / 4;
    const int k4 = (M_TOT * NKVD) / 4;
    split2_kernel<<<(q4 + 255) / 256, 256>>>(qb, qhp, qlp, QSC, q4);
    split2_kernel<<<(k4 + 255) / 256, 256>>>(kb, khp, klp, 1.0f, k4);
    vt_kernel<<<(B_ * NKV_ * (HD_ / 4) * S_ + 255) / 256, 256>>>(vb, vthp, vtlp);

    cudaFuncSetAttribute(flash_tc, cudaFuncAttributeMaxDynamicSharedMemorySize,
                         FLASH_SMEM_BYTES);
    flash_tc<<<dim3(S_ / 128, NH_, B_), 256, FLASH_SMEM_BYTES>>>(
        qhp, qlp, khp, klp, vthp, vtlp, ob);

    // output projection (all cols < 4096 -> routed to C0 = out)
    cvtH_kernel<<<(big4 + 255) / 256, 256>>>(ob, o2, big4);
    hgemm_nt<<<dim3(HID_ / 128, M_TOT / 128), 256>>>(o2, wo2, out, out, out, M_TOT, HID_);
}

// round 13
// speedup vs baseline: 2.6975x; 1.2674x over previous
#include <cuda_runtime.h>
#include <cuda_bf16.h>
#include <cuda_fp16.h>
#include <math.h>
#include <stdint.h>

// Problem constants
#define B_  2
#define S_  2048
#define HID_ 4096
#define NH_ 32
#define NKV_ 8
#define HD_ 128
#define M_TOT (B_ * S_)          // 4096
#define NKVD (NKV_ * HD_)        // 1024
#define NQKV (HID_ + 2 * NKVD)   // 6144 fused QKV output cols

// fp32 scratch
__device__ float g_q[(size_t)M_TOT * NH_ * HD_];
__device__ float g_k[(size_t)M_TOT * NKVD];
__device__ float g_v[(size_t)M_TOT * NKVD];
__device__ float g_o[(size_t)M_TOT * NH_ * HD_];

// fp16 scratch for projections (single-term)
__device__ __half g_A2 [(size_t)M_TOT * HID_];
__device__ __half g_W3 [(size_t)NQKV  * HID_];   // fused [Wq;Wk;Wv]
__device__ __half g_Wo2[(size_t)HID_  * HID_];
__device__ __half g_O2 [(size_t)M_TOT * HID_];

// fp16 scratch for flash attention (single-term)
__device__ __half g_qh [(size_t)M_TOT * NH_  * HD_];
__device__ __half g_kh [(size_t)M_TOT * NKVD];
__device__ __half g_vth[(size_t)M_TOT * NKVD];   // [b][kvh][d][s]

// ---------------------------------------------------------------------------
struct alignas(8) HF4 { __half v[4]; };

// cvtH: fp32 -> fp16 flat
__global__ void cvtH_kernel(const float* __restrict__ src,
                            __half* __restrict__ dst, int total4) {
    int i = blockIdx.x * blockDim.x + threadIdx.x;
    if (i >= total4) return;
    float4 x = *(const float4*)(src + (size_t)i * 4);
    HF4 H;
    H.v[0] = __float2half_rn(x.x);
    H.v[1] = __float2half_rn(x.y);
    H.v[2] = __float2half_rn(x.z);
    H.v[3] = __float2half_rn(x.w);
    *(HF4*)(dst + (size_t)i * 4) = H;
}

// ropecvt: apply RoPE to fp32 q/k and write fp16 (q prescaled by qsc)
#define ROPE_TOTAL (B_ * S_ * (NH_ + NKV_) * 64)

__global__ void ropecvt_kernel(const float* __restrict__ q,
                               const float* __restrict__ k,
                               const int* __restrict__ pos_ids,
                               __half* __restrict__ qh,
                               __half* __restrict__ kh, float qsc) {
    int idx = blockIdx.x * blockDim.x + threadIdx.x;
    if (idx >= ROPE_TOTAL) return;
    int d    = idx & 63;
    int rest = idx >> 6;
    int head = rest % (NH_ + NKV_);
    rest    /= (NH_ + NKV_);
    int s = rest % S_;
    int b = rest / S_;

    float inv = powf(10000.0f, -(float)d * (1.0f / 64.0f));
    float ang = (float)pos_ids[s] * inv;
    float c = cosf(ang), sn = sinf(ang);

    if (head < NH_) {
        size_t o = ((size_t)(b * S_ + s) * NH_ + head) * HD_;
        float x1 = q[o + d], x2 = q[o + d + 64];
        qh[o + d]      = __float2half_rn((x1 * c - x2 * sn) * qsc);
        qh[o + d + 64] = __float2half_rn((x2 * c + x1 * sn) * qsc);
    } else {
        size_t o = ((size_t)(b * S_ + s) * NKV_ + (head - NH_)) * HD_;
        float x1 = k[o + d], x2 = k[o + d + 64];
        kh[o + d]      = __float2half_rn(x1 * c - x2 * sn);
        kh[o + d + 64] = __float2half_rn(x2 * c + x1 * sn);
    }
}

// V transpose+cvt: g_v [b*S+s][kvh][d] -> fp16 [b][kvh][d][s]
__global__ void vt_kernel(const float* __restrict__ v,
                          __half* __restrict__ th) {
    int i = blockIdx.x * blockDim.x + threadIdx.x;
    int s    = i % S_;
    int rest = i / S_;
    int d4   = rest % (HD_ / 4);
    rest    /= (HD_ / 4);
    int kvh  = rest % NKV_;
    int b    = rest / NKV_;
    float4 x = *(const float4*)(v + ((size_t)(b * S_ + s) * NKV_ + kvh) * HD_ + d4 * 4);
    float xs[4] = {x.x, x.y, x.z, x.w};
#pragma unroll
    for (int j = 0; j < 4; j++) {
        size_t o = ((size_t)(b * NKV_ + kvh) * HD_ + d4 * 4 + j) * S_ + s;
        th[o] = __float2half_rn(xs[j]);
    }
}

// ---------------------------------------------------------------------------
// mma / ldmatrix helpers
// ---------------------------------------------------------------------------
__device__ __forceinline__ void ldsm4(uint32_t* r, uint32_t addr) {
    asm volatile("ldmatrix.sync.aligned.m8n8.x4.shared.b16 {%0,%1,%2,%3}, [%4];\n"
                 : "=r"(r[0]), "=r"(r[1]), "=r"(r[2]), "=r"(r[3]) : "r"(addr));
}
__device__ __forceinline__ void mma_f16(float* c, const uint32_t* a,
                                        uint32_t b0, uint32_t b1) {
    asm volatile("mma.sync.aligned.m16n8k16.row.col.f32.f16.f16.f32 "
                 "{%0,%1,%2,%3}, {%4,%5,%6,%7}, {%8,%9}, {%0,%1,%2,%3};\n"
                 : "+f"(c[0]), "+f"(c[1]), "+f"(c[2]), "+f"(c[3])
                 : "r"(a[0]), "r"(a[1]), "r"(a[2]), "r"(a[3]), "r"(b0), "r"(b1));
}
__device__ __forceinline__ uint32_t cvt_f16x2(float lo, float hi) {
    uint32_t r;
    asm("cvt.rn.f16x2.f32 %0, %1, %2;" : "=r"(r) : "f"(hi), "f"(lo));
    return r;
}

// ---------------------------------------------------------------------------
// fp16 tensor-core GEMM (NT): 128x128x32 tile, 256 threads, warp tile 64x32,
// 3-stage cp.async. Epilogue routes 128-col tiles for QKV.
// ---------------------------------------------------------------------------
#define HG_BK 32
#define HG_LDS 40
#define HG_STAGE_ELEMS (128 * HG_LDS)
#define HG_STAGE_BYTES (HG_STAGE_ELEMS * 2)

__global__ __launch_bounds__(256, 2) void hgemm_nt(
    const __half* __restrict__ A, const __half* __restrict__ B,
    float* __restrict__ C0, float* __restrict__ C1, float* __restrict__ C2,
    int M, int K) {
    __shared__ __half As[3][HG_STAGE_ELEMS];
    __shared__ __half Bs[3][HG_STAGE_ELEMS];

    const int t    = threadIdx.x;
    const int lane = t & 31;
    const int w    = t >> 5;
    const int wm   = w >> 2;
    const int wn   = w & 3;

    const __half* Ab = A + (size_t)blockIdx.y * 128 * K;
    const __half* Bb = B + (size_t)blockIdx.x * 128 * K;

    const uint32_t as0 = (uint32_t)__cvta_generic_to_shared(&As[0][0]);
    const uint32_t bs0 = (uint32_t)__cvta_generic_to_shared(&Bs[0][0]);

    const int ldr = t >> 2;
    const int ldc = (t & 3) * 8;

    auto load_tile = [&](int kt, int st) {
#pragma unroll
        for (int it = 0; it < 2; it++) {
            int r = ldr + it * 64;
            const __half* ga = Ab + (size_t)r * K + kt * HG_BK + ldc;
            uint32_t sa = as0 + st * HG_STAGE_BYTES + (r * HG_LDS + ldc) * 2;
            asm volatile("cp.async.cg.shared.global [%0], [%1], 16;\n" :: "r"(sa), "l"(ga));
            const __half* gb = Bb + (size_t)r * K + kt * HG_BK + ldc;
            uint32_t sb = bs0 + st * HG_STAGE_BYTES + (r * HG_LDS + ldc) * 2;
            asm volatile("cp.async.cg.shared.global [%0], [%1], 16;\n" :: "r"(sb), "l"(gb));
        }
    };

    const int KT = K / HG_BK;
    load_tile(0, 0);
    asm volatile("cp.async.commit_group;\n");
    load_tile(1, 1);
    asm volatile("cp.async.commit_group;\n");

    float acc[4][4][4];
#pragma unroll
    for (int i = 0; i < 4; i++)
#pragma unroll
        for (int j = 0; j < 4; j++)
#pragma unroll
            for (int r = 0; r < 4; r++) acc[i][j][r] = 0.f;

    const int g  = lane >> 3;
    const int lr = lane & 7;
    const int a_row = ((g & 1) << 3) + lr;
    const int a_k   = (g >> 1) << 3;
    const int b_row = ((g >> 1) << 3) + lr;
    const int b_k   = (g & 1) << 3;

    for (int kt = 0; kt < KT; kt++) {
        asm volatile("cp.async.wait_group 1;\n");
        __syncthreads();
        if (kt + 2 < KT) load_tile(kt + 2, (kt + 2) % 3);
        asm volatile("cp.async.commit_group;\n");

        const int st = kt % 3;
        const uint32_t asb = as0 + st * HG_STAGE_BYTES;
        const uint32_t bsb = bs0 + st * HG_STAGE_BYTES;

#pragma unroll
        for (int ks = 0; ks < 2; ks++) {
            uint32_t af[4][4];
            uint32_t bf_[4][2];
#pragma unroll
            for (int mf = 0; mf < 4; mf++) {
                int row = wm * 64 + mf * 16 + a_row;
                ldsm4(af[mf], asb + (row * HG_LDS + ks * 16 + a_k) * 2);
            }
#pragma unroll
            for (int np = 0; np < 2; np++) {
                int row = wn * 32 + np * 16 + b_row;
                uint32_t tmp[4];
                ldsm4(tmp, bsb + (row * HG_LDS + ks * 16 + b_k) * 2);
                bf_[np*2][0] = tmp[0]; bf_[np*2][1] = tmp[1];
                bf_[np*2+1][0] = tmp[2]; bf_[np*2+1][1] = tmp[3];
            }
#pragma unroll
            for (int mf = 0; mf < 4; mf++)
#pragma unroll
                for (int nf = 0; nf < 4; nf++)
                    mma_f16(acc[mf][nf], af[mf], bf_[nf][0], bf_[nf][1]);
        }
    }

    // epilogue with QKV column routing (Q: 4096 cols, K: 1024, V: 1024)
    const int gc0 = blockIdx.x * 128;
    float* Cd; int cstride, cbase;
    if (gc0 < HID_)                { Cd = C0; cstride = NH_ * HD_; cbase = 0; }
    else if (gc0 < HID_ + NKVD)    { Cd = C1; cstride = NKVD;      cbase = HID_; }
    else                           { Cd = C2; cstride = NKVD;      cbase = HID_ + NKVD; }

#pragma unroll
    for (int mf = 0; mf < 4; mf++) {
        int row = blockIdx.y * 128 + wm * 64 + mf * 16 + (lane >> 2);
#pragma unroll
        for (int nf = 0; nf < 4; nf++) {
            int col = gc0 + wn * 32 + nf * 8 + (lane & 3) * 2 - cbase;
            float2 v0 = {acc[mf][nf][0], acc[mf][nf][1]};
            float2 v1 = {acc[mf][nf][2], acc[mf][nf][3]};
            *(float2*)&Cd[(size_t)row * cstride + col]       = v0;
            *(float2*)&Cd[(size_t)(row + 8) * cstride + col] = v1;
        }
    }
}

// ---------------------------------------------------------------------------
// Tensor-core flash attention, single-term fp16. BQ=128, BK=64, HD=128,
// 256 threads (8 warps x 16 q-rows). fp32 softmax in registers.
// ---------------------------------------------------------------------------
#define FQ_LDS 136
#define FV_LDS 72
#define F_Q 0
#define F_STAGE0 17408
#define F_STAGE (8704 + 9216)   // K 64x136 + Vt 128x72 = 17920 elems
#define F_K 0
#define F_VT 8704
#define FLASH_SMEM_ELEMS (F_STAGE0 + 2 * F_STAGE)   // 53248
#define FLASH_SMEM_BYTES (FLASH_SMEM_ELEMS * 2)     // 106496

__global__ __launch_bounds__(256, 1) void flash_tc(
    const __half* __restrict__ qh, const __half* __restrict__ kh,
    const __half* __restrict__ vth, float* __restrict__ o) {
    const int qt  = gridDim.x - 1 - blockIdx.x;
    const int h   = blockIdx.y;
    const int b   = blockIdx.z;
    const int kvh = h >> 2;

    extern __shared__ __half fsm[];
    const uint32_t sb = (uint32_t)__cvta_generic_to_shared(fsm);

    const int t    = threadIdx.x;
    const int lane = t & 31;
    const int w    = t >> 5;

    {   // Q tile: 128 rows x 128 cols fp16
        int r = t >> 1;
        const __half* gq = qh + ((size_t)(b * S_ + qt * 128 + r) * NH_ + h) * HD_;
#pragma unroll
        for (int j = 0; j < 8; j++) {
            int col = (t & 1) * 64 + j * 8;
            uint32_t sh = sb + (F_Q + r * FQ_LDS + col) * 2;
            asm volatile("cp.async.cg.shared.global [%0], [%1], 16;\n" :: "r"(sh), "l"(gq + col));
        }
        asm volatile("cp.async.commit_group;\n");
    }

    auto load_kv = [&](int kt, int st) {
        uint32_t stb = sb + (F_STAGE0 + st * F_STAGE) * 2;
        {   // K: 64 rows x 128 cols
            int r  = t >> 2;
            int cb = (t & 3) * 32;
            size_t go = ((size_t)(b * S_ + kt * 64 + r) * NKV_ + kvh) * HD_;
#pragma unroll
            for (int j = 0; j < 4; j++) {
                int col = cb + j * 8;
                asm volatile("cp.async.cg.shared.global [%0], [%1], 16;\n"
                             :: "r"(stb + (F_K + r * FQ_LDS + col) * 2), "l"(kh + go + col));
            }
        }
        {   // Vt: 128 rows (d) x 64 cols (s)
            int rv = t >> 1;
            int cv = (t & 1) * 32;
            size_t go = ((size_t)(b * NKV_ + kvh) * HD_ + rv) * S_ + kt * 64;
#pragma unroll
            for (int j = 0; j < 4; j++) {
                int col = cv + j * 8;
                asm volatile("cp.async.cg.shared.global [%0], [%1], 16;\n"
                             :: "r"(stb + (F_VT + rv * FV_LDS + col) * 2), "l"(vth + go + col));
            }
        }
    };

    const int ktmax = 2 * qt + 1;
    load_kv(0, 0);
    asm volatile("cp.async.commit_group;\n");
    if (ktmax >= 1) load_kv(1, 1);
    asm volatile("cp.async.commit_group;\n");

    const int g  = lane >> 3;
    const int lr = lane & 7;
    const int a_row = ((g & 1) << 3) + lr;
    const int a_k   = (g >> 1) << 3;
    const int b_row = ((g >> 1) << 3) + lr;
    const int b_k   = (g & 1) << 3;

    float out[16][4];
#pragma unroll
    for (int i = 0; i < 16; i++)
#pragma unroll
        for (int j = 0; j < 4; j++) out[i][j] = 0.f;
    float m0 = -INFINITY, m1 = -INFINITY, l0 = 0.f, l1 = 0.f;

    const int qrow_base = qt * 128 + w * 16;

    for (int kt = 0; kt <= ktmax; kt++) {
        asm volatile("cp.async.wait_group 1;\n");
        __syncthreads();
        const int st = kt & 1;
        const uint32_t stb = sb + (F_STAGE0 + st * F_STAGE) * 2;

        if (kt * 64 <= qrow_base + 15) {
            // ---- scores: 16x64 over d=128 ----
            float accs[8][4];
#pragma unroll
            for (int i = 0; i < 8; i++)
#pragma unroll
                for (int j = 0; j < 4; j++) accs[i][j] = 0.f;

#pragma unroll
            for (int kc = 0; kc < 8; kc++) {
                uint32_t aH[4];
                ldsm4(aH, sb + (F_Q + (w * 16 + a_row) * FQ_LDS + kc * 16 + a_k) * 2);
#pragma unroll
                for (int nf2 = 0; nf2 < 4; nf2++) {
                    uint32_t bh[4];
                    ldsm4(bh, stb + (F_K + (nf2 * 16 + b_row) * FQ_LDS + kc * 16 + b_k) * 2);
                    mma_f16(accs[nf2 * 2],     aH, bh[0], bh[1]);
                    mma_f16(accs[nf2 * 2 + 1], aH, bh[2], bh[3]);
                }
            }

            if (kt * 64 + 63 > qrow_base) {
                int r0 = qrow_base + (lane >> 2);
#pragma unroll
                for (int nf = 0; nf < 8; nf++) {
#pragma unroll
                    for (int e = 0; e < 4; e++) {
                        int col = kt * 64 + nf * 8 + (lane & 3) * 2 + (e & 1);
                        int row = r0 + (e >> 1) * 8;
                        if (col > row) accs[nf][e] = -1.0e30f;
                    }
                }
            }

            float mx0 = -INFINITY, mx1 = -INFINITY;
#pragma unroll
            for (int nf = 0; nf < 8; nf++) {
                mx0 = fmaxf(mx0, fmaxf(accs[nf][0], accs[nf][1]));
                mx1 = fmaxf(mx1, fmaxf(accs[nf][2], accs[nf][3]));
            }
            mx0 = fmaxf(mx0, __shfl_xor_sync(0xffffffffu, mx0, 1));
            mx0 = fmaxf(mx0, __shfl_xor_sync(0xffffffffu, mx0, 2));
            mx1 = fmaxf(mx1, __shfl_xor_sync(0xffffffffu, mx1, 1));
            mx1 = fmaxf(mx1, __shfl_xor_sync(0xffffffffu, mx1, 2));
            float mn0 = fmaxf(m0, mx0), mn1 = fmaxf(m1, mx1);
            float c0 = exp2f(m0 - mn0), c1 = exp2f(m1 - mn1);
            m0 = mn0; m1 = mn1;

            float s0 = 0.f, s1 = 0.f;
#pragma unroll
            for (int nf = 0; nf < 8; nf++) {
                accs[nf][0] = exp2f(accs[nf][0] - mn0);
                accs[nf][1] = exp2f(accs[nf][1] - mn0);
                accs[nf][2] = exp2f(accs[nf][2] - mn1);
                accs[nf][3] = exp2f(accs[nf][3] - mn1);
                s0 += accs[nf][0] + accs[nf][1];
                s1 += accs[nf][2] + accs[nf][3];
            }
            s0 += __shfl_xor_sync(0xffffffffu, s0, 1);
            s0 += __shfl_xor_sync(0xffffffffu, s0, 2);
            s1 += __shfl_xor_sync(0xffffffffu, s1, 1);
            s1 += __shfl_xor_sync(0xffffffffu, s1, 2);
            l0 = l0 * c0 + s0;
            l1 = l1 * c1 + s1;

            // ---- P fp16 A-fragments in registers ----
            uint32_t pH[4][4];
#pragma unroll
            for (int kc2 = 0; kc2 < 4; kc2++) {
#pragma unroll
                for (int q4 = 0; q4 < 4; q4++) {
                    int nf = kc2 * 2 + (q4 >> 1);
                    int e0 = (q4 & 1) * 2;
                    pH[kc2][q4] = cvt_f16x2(accs[nf][e0], accs[nf][e0 + 1]);
                }
            }

#pragma unroll
            for (int i = 0; i < 16; i++) {
                out[i][0] *= c0; out[i][1] *= c0;
                out[i][2] *= c1; out[i][3] *= c1;
            }

            // ---- PV: out += P @ V ----
#pragma unroll
            for (int kc2 = 0; kc2 < 4; kc2++) {
#pragma unroll
                for (int nd = 0; nd < 8; nd++) {
                    uint32_t bh[4];
                    ldsm4(bh, stb + (F_VT + (nd * 16 + b_row) * FV_LDS + kc2 * 16 + b_k) * 2);
                    mma_f16(out[nd * 2],     pH[kc2], bh[0], bh[1]);
                    mma_f16(out[nd * 2 + 1], pH[kc2], bh[2], bh[3]);
                }
            }
        }

        __syncthreads();
        if (kt + 2 <= ktmax) load_kv(kt + 2, st);
        asm volatile("cp.async.commit_group;\n");
    }

    float inv0 = 1.0f / l0, inv1 = 1.0f / l1;
    int r0 = qt * 128 + w * 16 + (lane >> 2);
#pragma unroll
    for (int nfd = 0; nfd < 16; nfd++) {
        int col = nfd * 8 + (lane & 3) * 2;
        float2 v0 = {out[nfd][0] * inv0, out[nfd][1] * inv0};
        float2 v1 = {out[nfd][2] * inv1, out[nfd][3] * inv1};
        *(float2*)&o[((size_t)(b * S_ + r0) * NH_ + h) * HD_ + col]       = v0;
        *(float2*)&o[((size_t)(b * S_ + r0 + 8) * NH_ + h) * HD_ + col]   = v1;
    }
}

// ---------------------------------------------------------------------------
// Launch
// ---------------------------------------------------------------------------
extern "C" void kernel_launch(void* const* d_in, const int* in_sizes, int n_in,
                              void* d_out, int out_size) {
    const float* hidden = (const float*)d_in[0];
    const int*   pos    = (const int*)  d_in[2];
    const float* wq     = (const float*)d_in[3];
    const float* wk     = (const float*)d_in[4];
    const float* wv     = (const float*)d_in[5];
    const float* wo     = (const float*)d_in[6];
    float* out = (float*)d_out;

    float *qb, *kb, *vb, *ob;
    __half *a2, *w3, *wo2, *o2, *qhp, *khp, *vthp;
    cudaGetSymbolAddress((void**)&qb, g_q);
    cudaGetSymbolAddress((void**)&kb, g_k);
    cudaGetSymbolAddress((void**)&vb, g_v);
    cudaGetSymbolAddress((void**)&ob, g_o);
    cudaGetSymbolAddress((void**)&a2, g_A2);
    cudaGetSymbolAddress((void**)&w3, g_W3);
    cudaGetSymbolAddress((void**)&wo2, g_Wo2);
    cudaGetSymbolAddress((void**)&o2, g_O2);
    cudaGetSymbolAddress((void**)&qhp, g_qh);
    cudaGetSymbolAddress((void**)&khp, g_kh);
    cudaGetSymbolAddress((void**)&vthp, g_vth);

    const int big4   = (M_TOT * HID_) / 4;
    const int small4 = (NKVD * HID_) / 4;
    cvtH_kernel<<<(big4 + 255) / 256, 256>>>(hidden, a2, big4);
    cvtH_kernel<<<(big4 + 255) / 256, 256>>>(wq, w3, big4);
    cvtH_kernel<<<(small4 + 255) / 256, 256>>>(wk, w3 + (size_t)HID_ * HID_, small4);
    cvtH_kernel<<<(small4 + 255) / 256, 256>>>(wv, w3 + (size_t)(HID_ + NKVD) * HID_, small4);
    cvtH_kernel<<<(big4 + 255) / 256, 256>>>(wo, wo2, big4);

    // fused QKV projection: N = 6144, K = 4096
    hgemm_nt<<<dim3(NQKV / 128, M_TOT / 128), 256>>>(a2, w3, qb, kb, vb, M_TOT, HID_);

    // fused rope + fp16 convert (Q prescaled by 1/sqrt(HD)*log2(e))
    const float QSC = 0.08838834764831845f * 1.4426950408889634f;
    ropecvt_kernel<<<(ROPE_TOTAL + 255) / 256, 256>>>(qb, kb, pos, qhp, khp, QSC);
    vt_kernel<<<(B_ * NKV_ * (HD_ / 4) * S_ + 255) / 256, 256>>>(vb, vthp);

    cudaFuncSetAttribute(flash_tc, cudaFuncAttributeMaxDynamicSharedMemorySize,
                         FLASH_SMEM_BYTES);
    flash_tc<<<dim3(S_ / 128, NH_, B_), 256, FLASH_SMEM_BYTES>>>(qhp, khp, vthp, ob);

    // output projection
    cvtH_kernel<<<(big4 + 255) / 256, 256>>>(ob, o2, big4);
    hgemm_nt<<<dim3(HID_ / 128, M_TOT / 128), 256>>>(o2, wo2, out, out, out, M_TOT, HID_);
}